// round 2
// baseline (speedup 1.0000x reference)
#include <cuda_runtime.h>
#include <cstdint>

#define BB 32
#define NN 8732
#define CC 21
#define N2 17464          // 2*NN
#define TOPK 200
#define KW 7              // ceil(TOPK/32)

// scratch (allocation-free rule: device globals)
__device__ float g_boxes[(size_t)BB * N2 * 4];        // [B][2N][4] xyxy
__device__ float g_scores[(size_t)BB * CC * N2];      // [B][C][2N]

__device__ __forceinline__ uint32_t f2o(float f) {
    uint32_t u = __float_as_uint(f);
    return (u & 0x80000000u) ? ~u : (u | 0x80000000u);
}
__device__ __forceinline__ float o2f(uint32_t u) {
    uint32_t b = (u & 0x80000000u) ? (u & 0x7FFFFFFFu) : ~u;
    return __uint_as_float(b);
}

// ---------------------------------------------------------------------------
// Kernel 1: decode boxes (both views, view2 flipped) + softmax both views
// ---------------------------------------------------------------------------
__global__ __launch_bounds__(256) void prep_kernel(
    const float* __restrict__ loc1, const float* __restrict__ conf1,
    const float* __restrict__ loc2, const float* __restrict__ conf2,
    const float* __restrict__ dbox)
{
    int idx = blockIdx.x * 256 + threadIdx.x;
    if (idx >= BB * NN) return;
    int b = idx / NN, n = idx % NN;

    float dcx = dbox[n * 4 + 0], dcy = dbox[n * 4 + 1];
    float dw  = dbox[n * 4 + 2], dh  = dbox[n * 4 + 3];

    // view 1 decode
    {
        const float* l = loc1 + (size_t)idx * 4;
        float cx = dcx + (l[0] * 0.1f) * dw;
        float cy = dcy + (l[1] * 0.1f) * dh;
        float w = dw * expf(l[2] * 0.2f);
        float h = dh * expf(l[3] * 0.2f);
        float* o = g_boxes + ((size_t)b * N2 + n) * 4;
        o[0] = cx - w * 0.5f; o[1] = cy - h * 0.5f;
        o[2] = cx + w * 0.5f; o[3] = cy + h * 0.5f;
    }
    // view 2 decode + horizontal flip: x1' = 1-x2, x2' = 1-x1
    {
        const float* l = loc2 + (size_t)idx * 4;
        float cx = dcx + (l[0] * 0.1f) * dw;
        float cy = dcy + (l[1] * 0.1f) * dh;
        float w = dw * expf(l[2] * 0.2f);
        float h = dh * expf(l[3] * 0.2f);
        float x1 = cx - w * 0.5f, x2 = cx + w * 0.5f;
        float* o = g_boxes + ((size_t)b * N2 + NN + n) * 4;
        o[0] = 1.0f - x2; o[1] = cy - h * 0.5f;
        o[2] = 1.0f - x1; o[3] = cy + h * 0.5f;
    }
    // softmax view 1 -> g_scores[b][c][n]
    {
        const float* cf = conf1 + (size_t)idx * CC;
        float mx = cf[0];
        #pragma unroll
        for (int j = 1; j < CC; ++j) mx = fmaxf(mx, cf[j]);
        float e[CC]; float sum = 0.0f;
        #pragma unroll
        for (int j = 0; j < CC; ++j) { e[j] = expf(cf[j] - mx); sum += e[j]; }
        float* sb = g_scores + (size_t)b * CC * N2 + n;
        #pragma unroll
        for (int j = 0; j < CC; ++j) sb[(size_t)j * N2] = e[j] / sum;
    }
    // softmax view 2 -> g_scores[b][c][NN + n]
    {
        const float* cf = conf2 + (size_t)idx * CC;
        float mx = cf[0];
        #pragma unroll
        for (int j = 1; j < CC; ++j) mx = fmaxf(mx, cf[j]);
        float e[CC]; float sum = 0.0f;
        #pragma unroll
        for (int j = 0; j < CC; ++j) { e[j] = expf(cf[j] - mx); sum += e[j]; }
        float* sb = g_scores + (size_t)b * CC * N2 + NN + n;
        #pragma unroll
        for (int j = 0; j < CC; ++j) sb[(size_t)j * N2] = e[j] / sum;
    }
}

// ---------------------------------------------------------------------------
// Kernel 2: per (b, class>=1): top-200 (stable), NMS, compacted output
// ---------------------------------------------------------------------------
__global__ __launch_bounds__(256) void nms_kernel(float* __restrict__ out)
{
    const int c = blockIdx.x + 1;   // classes 1..20
    const int b = blockIdx.y;
    const int tid = threadIdx.x;

    extern __shared__ uint32_t skey[];   // N2 orderable keys (69856 B)

    __shared__ uint32_t hist[256];
    __shared__ uint32_t sh_prefix;
    __shared__ int sh_kr;
    __shared__ int cand_cnt;
    __shared__ int eq_taken;
    __shared__ int warp_cnt[8];
    __shared__ uint32_t cand_key[256];
    __shared__ uint32_t cand_idx[256];
    __shared__ unsigned long long ck64[256];
    __shared__ float cbox[TOPK][4];
    __shared__ float cscore[TOPK];
    __shared__ uint32_t iou_mask[TOPK][KW];
    __shared__ uint32_t keepw[KW];

    // load + mask + convert to orderable uint
    const float* sc = g_scores + ((size_t)b * CC + c) * N2;
    for (int i = tid; i < N2; i += 256) {
        float s = sc[i];
        float m = (s > 0.01f) ? s : -1.0f;
        skey[i] = f2o(m);
    }
    __syncthreads();

    // MSB-first radix select of rank-200 pivot
    uint32_t prefix = 0; int kr = TOPK;
    for (int pass = 0; pass < 4; ++pass) {
        int shift = 24 - 8 * pass;
        hist[tid] = 0;
        __syncthreads();
        for (int i = tid; i < N2; i += 256) {
            uint32_t u = skey[i];
            bool match = (pass == 0) || ((u >> (shift + 8)) == prefix);
            if (match) atomicAdd(&hist[(u >> shift) & 0xFFu], 1u);
        }
        __syncthreads();
        if (tid == 0) {
            int acc = 0, bsel = 0;
            for (int bin = 255; bin >= 0; --bin) {
                int h = (int)hist[bin];
                if (acc + h >= kr) { bsel = bin; break; }
                acc += h;
            }
            sh_prefix = (prefix << 8) | (uint32_t)bsel;
            sh_kr = kr - acc;
        }
        __syncthreads();
        prefix = sh_prefix; kr = sh_kr;
        __syncthreads();
    }
    const uint32_t pivot = prefix;   // exact value at rank boundary

    // collect strictly-greater elements (order fixed by later sort)
    if (tid == 0) { cand_cnt = 0; eq_taken = 0; }
    __syncthreads();
    for (int i = tid; i < N2; i += 256) {
        uint32_t u = skey[i];
        if (u > pivot) {
            int p = atomicAdd(&cand_cnt, 1);
            cand_key[p] = u; cand_idx[p] = (uint32_t)i;
        }
    }
    __syncthreads();
    const int ngreater = cand_cnt;   // == TOPK - kr

    // collect first kr elements equal to pivot, in ascending index order
    for (int base = 0; base < N2; base += 256) {
        int i = base + tid;
        bool eq = (i < N2) && (skey[i] == pivot);
        unsigned bal = __ballot_sync(0xFFFFFFFFu, eq);
        int warp = tid >> 5, lane = tid & 31;
        if (lane == 0) warp_cnt[warp] = __popc(bal);
        __syncthreads();
        int woff = 0;
        #pragma unroll
        for (int w = 0; w < 8; ++w) if (w < warp) woff += warp_cnt[w];
        int rank = eq_taken + woff + __popc(bal & ((1u << lane) - 1u));
        if (eq && rank < kr) {
            cand_key[ngreater + rank] = pivot;
            cand_idx[ngreater + rank] = (uint32_t)i;
        }
        __syncthreads();
        if (tid == 0) {
            int tot = 0;
            #pragma unroll
            for (int w = 0; w < 8; ++w) tot += warp_cnt[w];
            eq_taken += tot;
        }
        __syncthreads();
        if (eq_taken >= kr) break;
    }
    // pad slots [200,256)
    if (tid >= TOPK) { cand_key[tid] = 0u; cand_idx[tid] = 0xFFFFFFFFu; }
    __syncthreads();

    // bitonic sort 256 composite keys (ascending); rank r = slot 255-r
    // composite: value (primary) then ~index (so desc-read => index ascending on ties)
    ck64[tid] = ((unsigned long long)cand_key[tid] << 32) | (uint32_t)(~cand_idx[tid]);
    __syncthreads();
    for (int k = 2; k <= 256; k <<= 1) {
        for (int j = k >> 1; j > 0; j >>= 1) {
            int ixj = tid ^ j;
            if (ixj > tid) {
                bool up = ((tid & k) == 0);
                unsigned long long a = ck64[tid], bb2 = ck64[ixj];
                if ((a > bb2) == up) { ck64[tid] = bb2; ck64[ixj] = a; }
            }
            __syncthreads();
        }
    }

    // gather sorted top-200 scores + boxes
    if (tid < TOPK) {
        unsigned long long v = ck64[255 - tid];
        uint32_t key = (uint32_t)(v >> 32);
        uint32_t i = ~((uint32_t)v);
        cscore[tid] = o2f(key);
        const float* bp = g_boxes + ((size_t)b * N2 + i) * 4;
        cbox[tid][0] = bp[0]; cbox[tid][1] = bp[1];
        cbox[tid][2] = bp[2]; cbox[tid][3] = bp[3];
    }
    __syncthreads();

    // IoU > 0.45 bitmask, one (row, word) per work item
    for (int t = tid; t < TOPK * KW; t += 256) {
        int j = t / KW, w = t % KW;
        float jx1 = cbox[j][0], jy1 = cbox[j][1], jx2 = cbox[j][2], jy2 = cbox[j][3];
        float ja = (jx2 - jx1) * (jy2 - jy1);
        uint32_t m = 0;
        int i0 = w * 32;
        #pragma unroll 4
        for (int q = 0; q < 32; ++q) {
            int i = i0 + q;
            if (i >= TOPK) break;
            float x1 = fmaxf(jx1, cbox[i][0]);
            float y1 = fmaxf(jy1, cbox[i][1]);
            float x2 = fminf(jx2, cbox[i][2]);
            float y2 = fminf(jy2, cbox[i][3]);
            float inter = fmaxf(x2 - x1, 0.0f) * fmaxf(y2 - y1, 0.0f);
            float ia = (cbox[i][2] - cbox[i][0]) * (cbox[i][3] - cbox[i][1]);
            float iou = inter / (ja + ia - inter);
            if (iou > 0.45f) m |= (1u << q);
        }
        iou_mask[j][w] = m;
    }
    __syncthreads();

    // serial greedy NMS scan (exact reference semantics), pure bit ops
    if (tid == 0) {
        uint32_t sup[KW] = {0}, kp[KW] = {0};
        for (int j = 0; j < TOPK; ++j) {
            int w = j >> 5, bit = j & 31;
            if (cscore[j] > 0.01f && !((sup[w] >> bit) & 1u)) {
                kp[w] |= 1u << bit;
                #pragma unroll
                for (int q = 0; q < KW; ++q) sup[q] |= iou_mask[j][q];
            }
        }
        #pragma unroll
        for (int q = 0; q < KW; ++q) keepw[q] = kp[q];
    }
    __syncthreads();

    // compacted writes: pos = popcount of keeps before me
    if (tid < TOPK) {
        int w = tid >> 5, bit = tid & 31;
        if ((keepw[w] >> bit) & 1u) {
            int pos = __popc(keepw[w] & ((1u << bit) - 1u));
            for (int q = 0; q < w; ++q) pos += __popc(keepw[q]);
            float* op = out + (((size_t)b * CC + c) * TOPK + pos) * 5;
            op[0] = cscore[tid];
            op[1] = cbox[tid][0]; op[2] = cbox[tid][1];
            op[3] = cbox[tid][2]; op[4] = cbox[tid][3];
        }
    }
}

// ---------------------------------------------------------------------------
extern "C" void kernel_launch(void* const* d_in, const int* in_sizes, int n_in,
                              void* d_out, int out_size) {
    const float* loc1  = (const float*)d_in[0];
    const float* conf1 = (const float*)d_in[1];
    const float* loc2  = (const float*)d_in[2];
    const float* conf2 = (const float*)d_in[3];
    const float* dbox  = (const float*)d_in[4];
    float* out = (float*)d_out;

    cudaMemsetAsync(d_out, 0, (size_t)out_size * sizeof(float), 0);

    int total = BB * NN;
    prep_kernel<<<(total + 255) / 256, 256>>>(loc1, conf1, loc2, conf2, dbox);

    cudaFuncSetAttribute(nms_kernel, cudaFuncAttributeMaxDynamicSharedMemorySize,
                         N2 * (int)sizeof(uint32_t));
    dim3 grid(CC - 1, BB);
    nms_kernel<<<grid, 256, N2 * sizeof(uint32_t)>>>(out);
}

// round 4
// speedup vs baseline: 1.5559x; 1.5559x over previous
#include <cuda_runtime.h>
#include <cstdint>

#define BB 32
#define NN 8732
#define CC 21
#define N2 17464          // 2*NN
#define TOPK 200
#define KW 7              // ceil(TOPK/32)
#define NT 512            // threads per nms block
#define EQCAP 64

// dynamic smem layout (bytes):
//   [0, 69856)        skey[N2]            (phase 1; dead after collection)
//   [69856, 70880)    cand_key[256]       \  later reused as ck64[256]
//   [70880, 71904)    cand_idx[256]       /  (8B aligned @69856)
//   [71904, 72160)    eqidx[EQCAP]
//   phase 2 aliases over skey region:
//   [0, 3200)         cbox[200][4]
//   [3200, 4000)      cscore[200]
//   [4000, 9600)      iou_mask[200][KW]
#define DYN_BYTES 72160

// scratch (allocation-free rule: device globals)
__device__ float g_boxes[(size_t)BB * N2 * 4];        // [B][2N][4] xyxy
__device__ float g_scores[(size_t)BB * CC * N2];      // [B][C][2N]

__device__ __forceinline__ uint32_t f2o(float f) {
    uint32_t u = __float_as_uint(f);
    return (u & 0x80000000u) ? ~u : (u | 0x80000000u);
}
__device__ __forceinline__ float o2f(uint32_t u) {
    uint32_t b = (u & 0x80000000u) ? (u & 0x7FFFFFFFu) : ~u;
    return __uint_as_float(b);
}

// ---------------------------------------------------------------------------
// Kernel 1: decode boxes (both views, view2 flipped) + softmax both views
// ---------------------------------------------------------------------------
__global__ __launch_bounds__(256) void prep_kernel(
    const float* __restrict__ loc1, const float* __restrict__ conf1,
    const float* __restrict__ loc2, const float* __restrict__ conf2,
    const float* __restrict__ dbox)
{
    int idx = blockIdx.x * 256 + threadIdx.x;
    if (idx >= BB * NN) return;
    int b = idx / NN, n = idx % NN;

    float4 d4 = ((const float4*)dbox)[n];
    float dcx = d4.x, dcy = d4.y, dw = d4.z, dh = d4.w;

    {
        float4 l = ((const float4*)loc1)[idx];
        float cx = dcx + (l.x * 0.1f) * dw;
        float cy = dcy + (l.y * 0.1f) * dh;
        float w = dw * expf(l.z * 0.2f);
        float h = dh * expf(l.w * 0.2f);
        float4 o;
        o.x = cx - w * 0.5f; o.y = cy - h * 0.5f;
        o.z = cx + w * 0.5f; o.w = cy + h * 0.5f;
        ((float4*)g_boxes)[(size_t)b * N2 + n] = o;
    }
    {
        float4 l = ((const float4*)loc2)[idx];
        float cx = dcx + (l.x * 0.1f) * dw;
        float cy = dcy + (l.y * 0.1f) * dh;
        float w = dw * expf(l.z * 0.2f);
        float h = dh * expf(l.w * 0.2f);
        float x1 = cx - w * 0.5f, x2 = cx + w * 0.5f;
        float4 o;
        o.x = 1.0f - x2; o.y = cy - h * 0.5f;
        o.z = 1.0f - x1; o.w = cy + h * 0.5f;
        ((float4*)g_boxes)[(size_t)b * N2 + NN + n] = o;
    }
    {
        const float* cf = conf1 + (size_t)idx * CC;
        float mx = cf[0];
        #pragma unroll
        for (int j = 1; j < CC; ++j) mx = fmaxf(mx, cf[j]);
        float e[CC]; float sum = 0.0f;
        #pragma unroll
        for (int j = 0; j < CC; ++j) { e[j] = expf(cf[j] - mx); sum += e[j]; }
        float* sb = g_scores + (size_t)b * CC * N2 + n;
        #pragma unroll
        for (int j = 0; j < CC; ++j) sb[(size_t)j * N2] = e[j] / sum;
    }
    {
        const float* cf = conf2 + (size_t)idx * CC;
        float mx = cf[0];
        #pragma unroll
        for (int j = 1; j < CC; ++j) mx = fmaxf(mx, cf[j]);
        float e[CC]; float sum = 0.0f;
        #pragma unroll
        for (int j = 0; j < CC; ++j) { e[j] = expf(cf[j] - mx); sum += e[j]; }
        float* sb = g_scores + (size_t)b * CC * N2 + NN + n;
        #pragma unroll
        for (int j = 0; j < CC; ++j) sb[(size_t)j * N2] = e[j] / sum;
    }
}

// ---------------------------------------------------------------------------
// Kernel 2: per (b, class>=1): top-200 (stable), NMS, compacted output
// ---------------------------------------------------------------------------
__global__ __launch_bounds__(NT) void nms_kernel(float* __restrict__ out)
{
    const int c = blockIdx.x + 1;   // classes 1..20
    const int b = blockIdx.y;
    const int tid = threadIdx.x;

    extern __shared__ unsigned char dynsm[];
    uint32_t* skey = (uint32_t*)dynsm;                                   // [N2]
    uint32_t* cand_key = (uint32_t*)(dynsm + 69856);                     // [256]
    uint32_t* cand_idx = (uint32_t*)(dynsm + 70880);                     // [256]
    unsigned long long* ck64 = (unsigned long long*)(dynsm + 69856);     // [256] (aliases cand_*)
    uint32_t* eqidx = (uint32_t*)(dynsm + 71904);                        // [EQCAP]
    // phase-2 aliases (over skey region, only used after skey dead)
    float* cbox = (float*)dynsm;                                         // [200][4]
    float* cscore = (float*)(dynsm + 3200);                              // [200]
    uint32_t* iou_mask = (uint32_t*)(dynsm + 4000);                      // [200][KW]

    __shared__ uint32_t hist[256];
    __shared__ uint32_t sh_prefix;
    __shared__ int sh_kr;
    __shared__ int cand_cnt;
    __shared__ int eq_cnt;
    __shared__ int eq_taken;
    __shared__ int sh_used;
    __shared__ int warp_cnt[NT / 32];
    __shared__ uint32_t keepw[KW];

    // ---- load + threshold-mask + orderable-uint conversion (vectorized) ----
    const float* sc = g_scores + ((size_t)b * CC + c) * N2;
    const float4* sc4 = (const float4*)sc;
    uint4* sk4 = (uint4*)skey;
    for (int i = tid; i < N2 / 4; i += NT) {
        float4 v = sc4[i];
        uint4 o;
        o.x = f2o((v.x > 0.01f) ? v.x : -1.0f);
        o.y = f2o((v.y > 0.01f) ? v.y : -1.0f);
        o.z = f2o((v.z > 0.01f) ? v.z : -1.0f);
        o.w = f2o((v.w > 0.01f) ? v.w : -1.0f);
        sk4[i] = o;
    }
    __syncthreads();

    // ---- MSB-first radix select of rank-200 pivot ----
    const int NLOOP = ((N2 + NT - 1) / NT) * NT;
    uint32_t prefix = 0; int kr = TOPK;
    for (int pass = 0; pass < 4; ++pass) {
        int shift = 24 - 8 * pass;
        if (tid < 256) hist[tid] = 0;
        __syncthreads();
        // histogram with warp-aggregated atomics (scores cluster in few bins)
        for (int i = tid; i < NLOOP; i += NT) {
            bool inb = i < N2;
            uint32_t u = inb ? skey[i] : 0u;
            bool match = inb && ((pass == 0) || ((u >> (shift + 8)) == prefix));
            uint32_t bin = (u >> shift) & 0xFFu;
            uint32_t key = match ? bin : 0xFFFFFFFFu;
            uint32_t peers = __match_any_sync(0xFFFFFFFFu, key);
            int leader = __ffs(peers) - 1;
            if (match && (tid & 31) == leader)
                atomicAdd(&hist[bin], (uint32_t)__popc(peers));
        }
        __syncthreads();
        // parallel suffix-sum (in place, Hillis-Steele)
        for (int d = 1; d < 256; d <<= 1) {
            uint32_t t = 0;
            if (tid < 256 && tid + d < 256) t = hist[tid + d];
            __syncthreads();
            if (tid < 256) hist[tid] += t;
            __syncthreads();
        }
        // pick bin: largest bin with suffix >= kr
        if (tid < 256) {
            uint32_t S = hist[tid];
            uint32_t Snext = (tid < 255) ? hist[tid + 1] : 0u;
            if ((int)S >= kr && (int)Snext < kr) {
                sh_prefix = (prefix << 8) | (uint32_t)tid;
                sh_kr = kr - (int)Snext;
            }
        }
        __syncthreads();
        prefix = sh_prefix; kr = sh_kr;
        __syncthreads();
    }
    const uint32_t pivot = prefix;   // exact 32-bit value at rank boundary

    // ---- collect strictly-greater + equal elements ----
    if (tid == 0) { cand_cnt = 0; eq_cnt = 0; eq_taken = 0; }
    __syncthreads();
    for (int i = tid; i < N2; i += NT) {
        uint32_t u = skey[i];
        if (u > pivot) {
            int p = atomicAdd(&cand_cnt, 1);
            cand_key[p] = u; cand_idx[p] = (uint32_t)i;
        } else if (u == pivot) {
            int p = atomicAdd(&eq_cnt, 1);
            if (p < EQCAP) eqidx[p] = (uint32_t)i;
        }
    }
    __syncthreads();
    const int ngreater = cand_cnt;          // == TOPK - kr by radix invariant
    const int neq = eq_cnt;
    const int avail = 256 - ngreater;
    const int cap = (EQCAP < avail) ? EQCAP : avail;

    if (neq <= cap) {
        // all equals captured; sort below orders ties by ascending index
        if (tid < neq) {
            cand_key[ngreater + tid] = pivot;
            cand_idx[ngreater + tid] = eqidx[tid];
        }
        if (tid == 0) sh_used = ngreater + neq;
    } else {
        // exact ordered fallback (first kr equals in ascending index order)
        for (int base = 0; base < N2; base += NT) {
            int i = base + tid;
            bool eq = (i < N2) && (skey[i] == pivot);
            unsigned bal = __ballot_sync(0xFFFFFFFFu, eq);
            int warp = tid >> 5, lane = tid & 31;
            if (lane == 0) warp_cnt[warp] = __popc(bal);
            __syncthreads();
            int woff = 0;
            #pragma unroll
            for (int w = 0; w < NT / 32; ++w) if (w < warp) woff += warp_cnt[w];
            int rank = eq_taken + woff + __popc(bal & ((1u << lane) - 1u));
            if (eq && rank < kr) {
                cand_key[ngreater + rank] = pivot;
                cand_idx[ngreater + rank] = (uint32_t)i;
            }
            __syncthreads();
            if (tid == 0) {
                int tot = 0;
                #pragma unroll
                for (int w = 0; w < NT / 32; ++w) tot += warp_cnt[w];
                eq_taken += tot;
            }
            __syncthreads();
            if (eq_taken >= kr) break;
        }
        if (tid == 0) sh_used = ngreater + kr;
    }
    __syncthreads();
    const int used = sh_used;

    // ---- build composite keys in place (ck64 aliases cand_* region) ----
    uint32_t mykey = 0, myidx = 0xFFFFFFFFu;
    if (tid < 256 && tid < used) { mykey = cand_key[tid]; myidx = cand_idx[tid]; }
    __syncthreads();
    if (tid < 256)
        ck64[tid] = ((unsigned long long)mykey << 32) | (uint32_t)(~myidx);
    __syncthreads();

    // ---- bitonic sort 256 (ascending); rank r = slot 255-r
    for (int k = 2; k <= 256; k <<= 1) {
        for (int j = k >> 1; j > 0; j >>= 1) {
            if (tid < 256) {
                int ixj = tid ^ j;
                if (ixj > tid) {
                    bool up = ((tid & k) == 0);
                    unsigned long long a = ck64[tid], bb2 = ck64[ixj];
                    if ((a > bb2) == up) { ck64[tid] = bb2; ck64[ixj] = a; }
                }
            }
            __syncthreads();
        }
    }

    // ---- gather sorted top-200 (cbox/cscore alias dead skey region) ----
    if (tid < TOPK) {
        unsigned long long v = ck64[255 - tid];
        uint32_t key = (uint32_t)(v >> 32);
        uint32_t i = ~((uint32_t)v);
        cscore[tid] = o2f(key);
        const float4 bp = ((const float4*)g_boxes)[(size_t)b * N2 + i];
        cbox[tid * 4 + 0] = bp.x; cbox[tid * 4 + 1] = bp.y;
        cbox[tid * 4 + 2] = bp.z; cbox[tid * 4 + 3] = bp.w;
    }
    __syncthreads();

    // ---- IoU > 0.45 bitmask ----
    for (int t = tid; t < TOPK * KW; t += NT) {
        int j = t / KW, w = t % KW;
        float jx1 = cbox[j * 4 + 0], jy1 = cbox[j * 4 + 1];
        float jx2 = cbox[j * 4 + 2], jy2 = cbox[j * 4 + 3];
        float ja = (jx2 - jx1) * (jy2 - jy1);
        uint32_t m = 0;
        int i0 = w * 32;
        #pragma unroll 4
        for (int q = 0; q < 32; ++q) {
            int i = i0 + q;
            if (i >= TOPK) break;
            float x1 = fmaxf(jx1, cbox[i * 4 + 0]);
            float y1 = fmaxf(jy1, cbox[i * 4 + 1]);
            float x2 = fminf(jx2, cbox[i * 4 + 2]);
            float y2 = fminf(jy2, cbox[i * 4 + 3]);
            float inter = fmaxf(x2 - x1, 0.0f) * fmaxf(y2 - y1, 0.0f);
            float ia = (cbox[i * 4 + 2] - cbox[i * 4 + 0]) * (cbox[i * 4 + 3] - cbox[i * 4 + 1]);
            float iou = inter / (ja + ia - inter);
            if (iou > 0.45f) m |= (1u << q);
        }
        iou_mask[j * KW + w] = m;
    }
    __syncthreads();

    // ---- serial greedy NMS scan (exact reference semantics) ----
    if (tid == 0) {
        uint32_t sup[KW] = {0}, kp[KW] = {0};
        for (int j = 0; j < TOPK; ++j) {
            int w = j >> 5, bit = j & 31;
            if (cscore[j] > 0.01f && !((sup[w] >> bit) & 1u)) {
                kp[w] |= 1u << bit;
                #pragma unroll
                for (int q = 0; q < KW; ++q) sup[q] |= iou_mask[j * KW + q];
            }
        }
        #pragma unroll
        for (int q = 0; q < KW; ++q) keepw[q] = kp[q];
    }
    __syncthreads();

    // ---- compacted writes ----
    if (tid < TOPK) {
        int w = tid >> 5, bit = tid & 31;
        if ((keepw[w] >> bit) & 1u) {
            int pos = __popc(keepw[w] & ((1u << bit) - 1u));
            for (int q = 0; q < w; ++q) pos += __popc(keepw[q]);
            float* op = out + (((size_t)b * CC + c) * TOPK + pos) * 5;
            op[0] = cscore[tid];
            op[1] = cbox[tid * 4 + 0]; op[2] = cbox[tid * 4 + 1];
            op[3] = cbox[tid * 4 + 2]; op[4] = cbox[tid * 4 + 3];
        }
    }
}

// ---------------------------------------------------------------------------
extern "C" void kernel_launch(void* const* d_in, const int* in_sizes, int n_in,
                              void* d_out, int out_size) {
    const float* loc1  = (const float*)d_in[0];
    const float* conf1 = (const float*)d_in[1];
    const float* loc2  = (const float*)d_in[2];
    const float* conf2 = (const float*)d_in[3];
    const float* dbox  = (const float*)d_in[4];
    float* out = (float*)d_out;

    cudaMemsetAsync(d_out, 0, (size_t)out_size * sizeof(float), 0);

    int total = BB * NN;
    prep_kernel<<<(total + 255) / 256, 256>>>(loc1, conf1, loc2, conf2, dbox);

    cudaFuncSetAttribute(nms_kernel, cudaFuncAttributeMaxDynamicSharedMemorySize,
                         DYN_BYTES);
    dim3 grid(CC - 1, BB);
    nms_kernel<<<grid, NT, DYN_BYTES>>>(out);
}

// round 5
// speedup vs baseline: 1.7095x; 1.0987x over previous
#include <cuda_runtime.h>
#include <cstdint>

#define BB 32
#define NN 8732
#define CC 21
#define N2 17464          // 2*NN
#define NV (N2/4)         // 4366 float4s
#define TOPK 200
#define KW 7              // ceil(TOPK/32)
#define NT 512
#define NW (NT/32)
#define EQCAP 64
#define CCAP 1024

// scratch (allocation-free rule: device globals)
__device__ float g_boxes[(size_t)BB * N2 * 4];        // [B][2N][4] xyxy
__device__ float g_scores[(size_t)BB * CC * N2];      // [B][C][2N]

__device__ __forceinline__ uint32_t f2o(float f) {
    uint32_t u = __float_as_uint(f);
    return (u & 0x80000000u) ? ~u : (u | 0x80000000u);
}
__device__ __forceinline__ float o2f(uint32_t u) {
    uint32_t b = (u & 0x80000000u) ? (u & 0x7FFFFFFFu) : ~u;
    return __uint_as_float(b);
}

// warp-aggregated histogram add; requires fully-converged warp (padded loops)
__device__ __forceinline__ void hist_add(uint32_t* hist, uint32_t bin, bool active) {
    uint32_t key = active ? bin : 0xFFFFFFFFu;
    uint32_t peers = __match_any_sync(0xFFFFFFFFu, key);
    if (active && ((threadIdx.x & 31) == (uint32_t)(__ffs(peers) - 1)))
        atomicAdd(&hist[bin], (uint32_t)__popc(peers));
}

// ---------------------------------------------------------------------------
// Kernel 1: decode boxes (both views, view2 flipped) + softmax both views
// ---------------------------------------------------------------------------
__global__ __launch_bounds__(256) void prep_kernel(
    const float* __restrict__ loc1, const float* __restrict__ conf1,
    const float* __restrict__ loc2, const float* __restrict__ conf2,
    const float* __restrict__ dbox)
{
    int idx = blockIdx.x * 256 + threadIdx.x;
    if (idx >= BB * NN) return;
    int b = idx / NN, n = idx % NN;

    float4 d4 = ((const float4*)dbox)[n];
    float dcx = d4.x, dcy = d4.y, dw = d4.z, dh = d4.w;

    {
        float4 l = ((const float4*)loc1)[idx];
        float cx = dcx + (l.x * 0.1f) * dw;
        float cy = dcy + (l.y * 0.1f) * dh;
        float w = dw * expf(l.z * 0.2f);
        float h = dh * expf(l.w * 0.2f);
        float4 o;
        o.x = cx - w * 0.5f; o.y = cy - h * 0.5f;
        o.z = cx + w * 0.5f; o.w = cy + h * 0.5f;
        ((float4*)g_boxes)[(size_t)b * N2 + n] = o;
    }
    {
        float4 l = ((const float4*)loc2)[idx];
        float cx = dcx + (l.x * 0.1f) * dw;
        float cy = dcy + (l.y * 0.1f) * dh;
        float w = dw * expf(l.z * 0.2f);
        float h = dh * expf(l.w * 0.2f);
        float x1 = cx - w * 0.5f, x2 = cx + w * 0.5f;
        float4 o;
        o.x = 1.0f - x2; o.y = cy - h * 0.5f;
        o.z = 1.0f - x1; o.w = cy + h * 0.5f;
        ((float4*)g_boxes)[(size_t)b * N2 + NN + n] = o;
    }
    {
        const float* cf = conf1 + (size_t)idx * CC;
        float mx = cf[0];
        #pragma unroll
        for (int j = 1; j < CC; ++j) mx = fmaxf(mx, cf[j]);
        float e[CC]; float sum = 0.0f;
        #pragma unroll
        for (int j = 0; j < CC; ++j) { e[j] = expf(cf[j] - mx); sum += e[j]; }
        float* sb = g_scores + (size_t)b * CC * N2 + n;
        #pragma unroll
        for (int j = 0; j < CC; ++j) sb[(size_t)j * N2] = e[j] / sum;
    }
    {
        const float* cf = conf2 + (size_t)idx * CC;
        float mx = cf[0];
        #pragma unroll
        for (int j = 1; j < CC; ++j) mx = fmaxf(mx, cf[j]);
        float e[CC]; float sum = 0.0f;
        #pragma unroll
        for (int j = 0; j < CC; ++j) { e[j] = expf(cf[j] - mx); sum += e[j]; }
        float* sb = g_scores + (size_t)b * CC * N2 + NN + n;
        #pragma unroll
        for (int j = 0; j < CC; ++j) sb[(size_t)j * N2] = e[j] / sum;
    }
}

// ---------------------------------------------------------------------------
// Kernel 2: per (b, class>=1): top-200 (stable), NMS, compacted output
// ---------------------------------------------------------------------------
__global__ __launch_bounds__(NT, 4) void nms_kernel(float* __restrict__ out)
{
    const int c = blockIdx.x + 1;   // classes 1..20
    const int b = blockIdx.y;
    const int tid = threadIdx.x;
    const int lane = tid & 31, warp = tid >> 5;

    __shared__ uint32_t hist[2048];
    __shared__ uint32_t compactv[CCAP];
    __shared__ uint32_t cand_key[256];
    __shared__ uint32_t cand_idx[256];
    __shared__ unsigned long long ck64[256];
    __shared__ uint32_t eqidx[EQCAP];
    __shared__ float cbox[TOPK * 4];
    __shared__ float cscore[TOPK];
    __shared__ uint32_t iou_mask[TOPK * KW];
    __shared__ uint32_t wsum[NW];
    __shared__ uint32_t sh_sel;
    __shared__ int sh_krem;
    __shared__ int ccnt, cand_cnt, eq_cnt, eq_taken, sh_used;
    __shared__ int warp_cnt[NW];
    __shared__ uint32_t validw[KW], keepw[KW];

    const float4* sc4 = (const float4*)(g_scores + ((size_t)b * CC + c) * N2);
    const float* sc = (const float*)sc4;

    // ---------------------------------------------------------------
    // block-wide boundary-bin selection from hist[bins]; bins in {2048,1024}
    // ---------------------------------------------------------------
    auto select_bin = [&](int bins, int kr) {
        int bpt = bins / NT;                 // 4 or 2
        int base = tid * bpt;
        uint32_t s = 0;
        for (int k = 0; k < bpt; ++k) s += hist[base + k];
        uint32_t v = s;                      // inclusive suffix within warp
        #pragma unroll
        for (int off = 1; off < 32; off <<= 1) {
            uint32_t o = __shfl_down_sync(0xFFFFFFFFu, v, off);
            if (lane + off < 32) v += o;
        }
        if (lane == 0) wsum[warp] = v;       // warp totals
        __syncthreads();
        if (tid < NW) {
            uint32_t wv = wsum[tid];
            #pragma unroll
            for (int off = 1; off < NW; off <<= 1) {
                uint32_t o = __shfl_down_sync((1u << NW) - 1u, wv, off);
                if (tid + off < NW) wv += o;
            }
            wsum[tid] = wv;                  // inclusive suffix of warp totals
        }
        __syncthreads();
        uint32_t warp_excl = (warp < NW - 1) ? wsum[warp + 1] : 0u;
        uint32_t t_excl = warp_excl + (v - s);   // suffix of threads strictly above
        if ((int)t_excl < kr && kr <= (int)(t_excl + s)) {
            uint32_t acc = t_excl;
            for (int k = bpt - 1; k >= 0; --k) {
                uint32_t h = hist[base + k];
                acc += h;
                if ((int)acc >= kr) { sh_sel = (uint32_t)(base + k); sh_krem = kr - (int)(acc - h); break; }
            }
        }
        __syncthreads();
    };

    const int NVL = ((NV + NT - 1) / NT) * NT;

    // ---- pass 0: 2048-bin histogram on bits[31:21], direct from global ----
    for (int i = tid; i < 2048; i += NT) hist[i] = 0;
    __syncthreads();
    for (int i = tid; i < NVL; i += NT) {
        bool inb = i < NV;
        float4 v = inb ? sc4[i] : make_float4(-1.f, -1.f, -1.f, -1.f);
        uint32_t u0 = f2o((v.x > 0.01f) ? v.x : -1.0f);
        uint32_t u1 = f2o((v.y > 0.01f) ? v.y : -1.0f);
        uint32_t u2 = f2o((v.z > 0.01f) ? v.z : -1.0f);
        uint32_t u3 = f2o((v.w > 0.01f) ? v.w : -1.0f);
        hist_add(hist, u0 >> 21, inb);
        hist_add(hist, u1 >> 21, inb);
        hist_add(hist, u2 >> 21, inb);
        hist_add(hist, u3 >> 21, inb);
    }
    __syncthreads();
    select_bin(2048, TOPK);
    const uint32_t sel0 = sh_sel;
    int kr = sh_krem;
    const int bincnt = (int)hist[sel0];
    const bool ovf = bincnt > CCAP;
    __syncthreads();

    // ---- compact the boundary bin's values into shared (values only) ----
    if (tid == 0) ccnt = 0;
    __syncthreads();
    if (!ovf) {
        for (int i = tid; i < NV; i += NT) {
            float4 v = sc4[i];
            uint32_t u[4] = { f2o((v.x > 0.01f) ? v.x : -1.0f),
                              f2o((v.y > 0.01f) ? v.y : -1.0f),
                              f2o((v.z > 0.01f) ? v.z : -1.0f),
                              f2o((v.w > 0.01f) ? v.w : -1.0f) };
            #pragma unroll
            for (int k = 0; k < 4; ++k)
                if ((u[k] >> 21) == sel0) {
                    int p = atomicAdd(&ccnt, 1);
                    compactv[p] = u[k];
                }
        }
    }
    __syncthreads();
    const int nc = ccnt;

    // ---- pass 1: 2048-bin histogram on bits[20:10] ----
    for (int i = tid; i < 2048; i += NT) hist[i] = 0;
    __syncthreads();
    if (!ovf) {
        const int NCL = ((nc + NT - 1) / NT) * NT;
        for (int i = tid; i < NCL; i += NT) {
            bool inb = i < nc;
            uint32_t u = inb ? compactv[i] : 0u;
            hist_add(hist, (u >> 10) & 0x7FFu, inb);
        }
    } else {
        for (int i = tid; i < NVL; i += NT) {
            bool inb = i < NV;
            float4 v = inb ? sc4[i] : make_float4(-1.f, -1.f, -1.f, -1.f);
            uint32_t u[4] = { f2o((v.x > 0.01f) ? v.x : -1.0f),
                              f2o((v.y > 0.01f) ? v.y : -1.0f),
                              f2o((v.z > 0.01f) ? v.z : -1.0f),
                              f2o((v.w > 0.01f) ? v.w : -1.0f) };
            #pragma unroll
            for (int k = 0; k < 4; ++k)
                hist_add(hist, (u[k] >> 10) & 0x7FFu, inb && ((u[k] >> 21) == sel0));
        }
    }
    __syncthreads();
    select_bin(2048, kr);
    const uint32_t sel1 = sh_sel;
    kr = sh_krem;
    const uint32_t prefix21 = (sel0 << 11) | sel1;
    __syncthreads();

    // ---- pass 2: 1024-bin histogram on bits[9:0] ----
    for (int i = tid; i < 1024; i += NT) hist[i] = 0;
    __syncthreads();
    if (!ovf) {
        const int NCL = ((nc + NT - 1) / NT) * NT;
        for (int i = tid; i < NCL; i += NT) {
            bool inb = i < nc;
            uint32_t u = inb ? compactv[i] : 0u;
            hist_add(hist, u & 0x3FFu, inb && (((u >> 10) & 0x7FFu) == sel1));
        }
    } else {
        for (int i = tid; i < NVL; i += NT) {
            bool inb = i < NV;
            float4 v = inb ? sc4[i] : make_float4(-1.f, -1.f, -1.f, -1.f);
            uint32_t u[4] = { f2o((v.x > 0.01f) ? v.x : -1.0f),
                              f2o((v.y > 0.01f) ? v.y : -1.0f),
                              f2o((v.z > 0.01f) ? v.z : -1.0f),
                              f2o((v.w > 0.01f) ? v.w : -1.0f) };
            #pragma unroll
            for (int k = 0; k < 4; ++k)
                hist_add(hist, u[k] & 0x3FFu, inb && ((u[k] >> 10) == prefix21));
        }
    }
    __syncthreads();
    select_bin(1024, kr);
    const uint32_t pivot = (prefix21 << 10) | sh_sel;
    kr = sh_krem;
    __syncthreads();

    // ---- collection pass (global): strictly-greater + equals ----
    if (tid == 0) { cand_cnt = 0; eq_cnt = 0; eq_taken = 0; }
    __syncthreads();
    for (int i = tid; i < NV; i += NT) {
        float4 v = sc4[i];
        uint32_t u[4] = { f2o((v.x > 0.01f) ? v.x : -1.0f),
                          f2o((v.y > 0.01f) ? v.y : -1.0f),
                          f2o((v.z > 0.01f) ? v.z : -1.0f),
                          f2o((v.w > 0.01f) ? v.w : -1.0f) };
        #pragma unroll
        for (int k = 0; k < 4; ++k) {
            if (u[k] > pivot) {
                int p = atomicAdd(&cand_cnt, 1);
                cand_key[p] = u[k]; cand_idx[p] = (uint32_t)(i * 4 + k);
            } else if (u[k] == pivot) {
                int p = atomicAdd(&eq_cnt, 1);
                if (p < EQCAP) eqidx[p] = (uint32_t)(i * 4 + k);
            }
        }
    }
    __syncthreads();
    const int ngreater = cand_cnt;          // == TOPK - kr by radix invariant
    const int neq = eq_cnt;
    const int avail = 256 - ngreater;
    const int cap = (EQCAP < avail) ? EQCAP : avail;

    if (neq <= cap) {
        if (tid < neq) {
            cand_key[ngreater + tid] = pivot;
            cand_idx[ngreater + tid] = eqidx[tid];
        }
        if (tid == 0) sh_used = ngreater + neq;
    } else {
        // exact ordered fallback: first kr equals in ascending index order
        for (int base = 0; base < N2; base += NT) {
            int i = base + tid;
            bool eq = false;
            if (i < N2) {
                float s = sc[i];
                uint32_t u = f2o((s > 0.01f) ? s : -1.0f);
                eq = (u == pivot);
            }
            unsigned bal = __ballot_sync(0xFFFFFFFFu, eq);
            if (lane == 0) warp_cnt[warp] = __popc(bal);
            __syncthreads();
            int woff = 0;
            #pragma unroll
            for (int w = 0; w < NW; ++w) if (w < warp) woff += warp_cnt[w];
            int rank = eq_taken + woff + __popc(bal & ((1u << lane) - 1u));
            if (eq && rank < kr) {
                cand_key[ngreater + rank] = pivot;
                cand_idx[ngreater + rank] = (uint32_t)i;
            }
            __syncthreads();
            if (tid == 0) {
                int tot = 0;
                #pragma unroll
                for (int w = 0; w < NW; ++w) tot += warp_cnt[w];
                eq_taken += tot;
            }
            __syncthreads();
            if (eq_taken >= kr) break;
        }
        if (tid == 0) sh_used = ngreater + kr;
    }
    __syncthreads();
    const int used = sh_used;

    // ---- composite keys: value desc primary, index asc on ties ----
    uint32_t mykey = 0, myidx = 0xFFFFFFFFu;
    if (tid < 256 && tid < used) { mykey = cand_key[tid]; myidx = cand_idx[tid]; }
    __syncthreads();
    if (tid < 256)
        ck64[tid] = ((unsigned long long)mykey << 32) | (uint32_t)(~myidx);
    __syncthreads();

    // ---- bitonic sort 256 ascending; rank r lives at slot 255-r ----
    for (int k = 2; k <= 256; k <<= 1) {
        for (int j = k >> 1; j > 0; j >>= 1) {
            if (tid < 256) {
                int ixj = tid ^ j;
                if (ixj > tid) {
                    bool up = ((tid & k) == 0);
                    unsigned long long a = ck64[tid], bb2 = ck64[ixj];
                    if ((a > bb2) == up) { ck64[tid] = bb2; ck64[ixj] = a; }
                }
            }
            __syncthreads();
        }
    }

    // ---- gather sorted top-200 scores + boxes ----
    if (tid < TOPK) {
        unsigned long long v = ck64[255 - tid];
        uint32_t key = (uint32_t)(v >> 32);
        uint32_t i = ~((uint32_t)v);
        cscore[tid] = o2f(key);
        const float4 bp = ((const float4*)g_boxes)[(size_t)b * N2 + i];
        cbox[tid * 4 + 0] = bp.x; cbox[tid * 4 + 1] = bp.y;
        cbox[tid * 4 + 2] = bp.z; cbox[tid * 4 + 3] = bp.w;
    }
    __syncthreads();

    // ---- IoU > 0.45 bitmask ----
    for (int t = tid; t < TOPK * KW; t += NT) {
        int j = t / KW, w = t % KW;
        float jx1 = cbox[j * 4 + 0], jy1 = cbox[j * 4 + 1];
        float jx2 = cbox[j * 4 + 2], jy2 = cbox[j * 4 + 3];
        float ja = (jx2 - jx1) * (jy2 - jy1);
        uint32_t m = 0;
        int i0 = w * 32;
        #pragma unroll 4
        for (int q = 0; q < 32; ++q) {
            int i = i0 + q;
            if (i >= TOPK) break;
            float x1 = fmaxf(jx1, cbox[i * 4 + 0]);
            float y1 = fmaxf(jy1, cbox[i * 4 + 1]);
            float x2 = fminf(jx2, cbox[i * 4 + 2]);
            float y2 = fminf(jy2, cbox[i * 4 + 3]);
            float inter = fmaxf(x2 - x1, 0.0f) * fmaxf(y2 - y1, 0.0f);
            float ia = (cbox[i * 4 + 2] - cbox[i * 4 + 0]) * (cbox[i * 4 + 3] - cbox[i * 4 + 1]);
            float iou = inter / (ja + ia - inter);
            if (iou > 0.45f) m |= (1u << q);
        }
        iou_mask[j * KW + w] = m;
    }
    // valid bitmap (score > thresh)
    {
        bool v = (tid < TOPK) && (cscore[tid] > 0.01f);
        uint32_t bal = __ballot_sync(0xFFFFFFFFu, v);
        if (lane == 0 && warp < KW) validw[warp] = bal;
    }
    __syncthreads();

    // ---- serial greedy NMS: skip-scan over set bits only ----
    if (tid == 0) {
        uint32_t sup[KW] = {0}, kp[KW] = {0};
        for (int w = 0; w < KW; ++w) {
            uint32_t rem = validw[w] & ~sup[w];
            while (rem) {
                int bit = __ffs(rem) - 1;
                int j = w * 32 + bit;
                kp[w] |= 1u << bit;
                #pragma unroll
                for (int q = 0; q < KW; ++q) sup[q] |= iou_mask[j * KW + q];
                uint32_t done = (bit >= 31) ? 0xFFFFFFFFu : ((2u << bit) - 1u);
                rem = validw[w] & ~sup[w] & ~done;
            }
        }
        #pragma unroll
        for (int q = 0; q < KW; ++q) keepw[q] = kp[q];
    }
    __syncthreads();

    // ---- compacted writes ----
    if (tid < TOPK) {
        int w = tid >> 5, bit = tid & 31;
        if ((keepw[w] >> bit) & 1u) {
            int pos = __popc(keepw[w] & ((1u << bit) - 1u));
            for (int q = 0; q < w; ++q) pos += __popc(keepw[q]);
            float* op = out + (((size_t)b * CC + c) * TOPK + pos) * 5;
            op[0] = cscore[tid];
            op[1] = cbox[tid * 4 + 0]; op[2] = cbox[tid * 4 + 1];
            op[3] = cbox[tid * 4 + 2]; op[4] = cbox[tid * 4 + 3];
        }
    }
}

// ---------------------------------------------------------------------------
extern "C" void kernel_launch(void* const* d_in, const int* in_sizes, int n_in,
                              void* d_out, int out_size) {
    const float* loc1  = (const float*)d_in[0];
    const float* conf1 = (const float*)d_in[1];
    const float* loc2  = (const float*)d_in[2];
    const float* conf2 = (const float*)d_in[3];
    const float* dbox  = (const float*)d_in[4];
    float* out = (float*)d_out;

    cudaMemsetAsync(d_out, 0, (size_t)out_size * sizeof(float), 0);

    int total = BB * NN;
    prep_kernel<<<(total + 255) / 256, 256>>>(loc1, conf1, loc2, conf2, dbox);

    dim3 grid(CC - 1, BB);
    nms_kernel<<<grid, NT>>>(out);
}

// round 6
// speedup vs baseline: 1.8237x; 1.0668x over previous
#include <cuda_runtime.h>
#include <cstdint>

#define BB 32
#define NN 8732
#define CC 21
#define N2 17464          // 2*NN
#define NV (N2/4)         // 4366 float4s
#define TOPK 200
#define KW 7              // ceil(TOPK/32)
#define NT 512
#define NW (NT/32)
#define CAP 1024

// scratch (allocation-free rule: device globals)
__device__ float g_boxes[(size_t)BB * N2 * 4];        // [B][2N][4] xyxy
__device__ float g_scores[(size_t)BB * CC * N2];      // [B][C][2N]

__device__ __forceinline__ uint32_t f2o(float f) {
    uint32_t u = __float_as_uint(f);
    return (u & 0x80000000u) ? ~u : (u | 0x80000000u);
}
__device__ __forceinline__ float o2f(uint32_t u) {
    uint32_t b = (u & 0x80000000u) ? (u & 0x7FFFFFFFu) : ~u;
    return __uint_as_float(b);
}

// ---------------------------------------------------------------------------
// Kernel 1: decode boxes (both views, view2 flipped) + softmax both views
// ---------------------------------------------------------------------------
__global__ __launch_bounds__(256) void prep_kernel(
    const float* __restrict__ loc1, const float* __restrict__ conf1,
    const float* __restrict__ loc2, const float* __restrict__ conf2,
    const float* __restrict__ dbox)
{
    int idx = blockIdx.x * 256 + threadIdx.x;
    if (idx >= BB * NN) return;
    int b = idx / NN, n = idx % NN;

    float4 d4 = ((const float4*)dbox)[n];
    float dcx = d4.x, dcy = d4.y, dw = d4.z, dh = d4.w;

    {
        float4 l = ((const float4*)loc1)[idx];
        float cx = dcx + (l.x * 0.1f) * dw;
        float cy = dcy + (l.y * 0.1f) * dh;
        float w = dw * expf(l.z * 0.2f);
        float h = dh * expf(l.w * 0.2f);
        float4 o;
        o.x = cx - w * 0.5f; o.y = cy - h * 0.5f;
        o.z = cx + w * 0.5f; o.w = cy + h * 0.5f;
        ((float4*)g_boxes)[(size_t)b * N2 + n] = o;
    }
    {
        float4 l = ((const float4*)loc2)[idx];
        float cx = dcx + (l.x * 0.1f) * dw;
        float cy = dcy + (l.y * 0.1f) * dh;
        float w = dw * expf(l.z * 0.2f);
        float h = dh * expf(l.w * 0.2f);
        float x1 = cx - w * 0.5f, x2 = cx + w * 0.5f;
        float4 o;
        o.x = 1.0f - x2; o.y = cy - h * 0.5f;
        o.z = 1.0f - x1; o.w = cy + h * 0.5f;
        ((float4*)g_boxes)[(size_t)b * N2 + NN + n] = o;
    }
    {
        const float* cf = conf1 + (size_t)idx * CC;
        float mx = cf[0];
        #pragma unroll
        for (int j = 1; j < CC; ++j) mx = fmaxf(mx, cf[j]);
        float e[CC]; float sum = 0.0f;
        #pragma unroll
        for (int j = 0; j < CC; ++j) { e[j] = expf(cf[j] - mx); sum += e[j]; }
        float* sb = g_scores + (size_t)b * CC * N2 + n;
        #pragma unroll
        for (int j = 0; j < CC; ++j) sb[(size_t)j * N2] = e[j] / sum;
    }
    {
        const float* cf = conf2 + (size_t)idx * CC;
        float mx = cf[0];
        #pragma unroll
        for (int j = 1; j < CC; ++j) mx = fmaxf(mx, cf[j]);
        float e[CC]; float sum = 0.0f;
        #pragma unroll
        for (int j = 0; j < CC; ++j) { e[j] = expf(cf[j] - mx); sum += e[j]; }
        float* sb = g_scores + (size_t)b * CC * N2 + NN + n;
        #pragma unroll
        for (int j = 0; j < CC; ++j) sb[(size_t)j * N2] = e[j] / sum;
    }
}

// ---------------------------------------------------------------------------
// Kernel 2: per (b, class>=1): top-200 (stable), NMS, compacted output
// ---------------------------------------------------------------------------
__global__ __launch_bounds__(NT, 4) void nms_kernel(float* __restrict__ out)
{
    const int c = blockIdx.x + 1;   // classes 1..20
    const int b = blockIdx.y;
    const int tid = threadIdx.x;
    const int lane = tid & 31, warp = tid >> 5;

    __shared__ uint32_t hist[256];
    __shared__ uint32_t wsum[8];
    __shared__ unsigned long long ck64[CAP];
    __shared__ float cbox[TOPK * 4];
    __shared__ float cscore[TOPK];
    __shared__ uint32_t iou_mask[TOPK * KW];
    __shared__ int sh_bf, sh_cntge, sh_above;
    __shared__ int ccnt, eq_taken;
    __shared__ int warp_cnt[NW];
    __shared__ uint32_t validw[KW], keepw[KW];

    const float4* sc4 = (const float4*)(g_scores + ((size_t)b * CC + c) * N2);
    const float* sc = (const float*)sc4;
    const uint32_t U01 = f2o(0.01f);

    uint32_t gLo = U01 + 1;       // candidate set = { u >= gLo }
    int shift = 18;
    int cnt_above = 0;            // count of elements above current bin range
    int cnt_ge = 0;
    int mode = 0;                 // 0 = collect all >= gLo; 1 = exact-tie terminal
    uint32_t pivot = 0;
    int kr = 0;

    // ---- boundary-bin search (typically exactly one iteration) ----
    for (;;) {
        if (tid < 256) hist[tid] = 0;
        if (tid == 0) sh_bf = -1;
        __syncthreads();
        // histogram of in-range elements; offset binning spreads atomics
        for (int i = tid; i < NV; i += NT) {
            float4 v = sc4[i];
            float vv[4] = { v.x, v.y, v.z, v.w };
            #pragma unroll
            for (int k = 0; k < 4; ++k) {
                if (vv[k] > 0.01f) {
                    uint32_t u = f2o(vv[k]);
                    if (u >= gLo) {
                        uint32_t rel = u - gLo;
                        if ((rel >> shift) < 256u)
                            atomicAdd(&hist[rel >> shift], 1u);
                    }
                }
            }
        }
        __syncthreads();
        // block suffix-scan over 256 bins
        uint32_t h = (tid < 256) ? hist[tid] : 0u;
        uint32_t v = h;
        #pragma unroll
        for (int off = 1; off < 32; off <<= 1) {
            uint32_t o = __shfl_down_sync(0xFFFFFFFFu, v, off);
            if (lane + off < 32) v += o;
        }
        if (tid < 256 && lane == 0) wsum[warp] = v;
        __syncthreads();
        if (warp == 0 && lane < 8) {
            uint32_t w8 = wsum[lane];
            #pragma unroll
            for (int off = 1; off < 8; off <<= 1) {
                uint32_t o = __shfl_down_sync(0xFFu, w8, off, 8);
                if (lane + off < 8) w8 += o;
            }
            wsum[lane] = w8;
        }
        __syncthreads();
        if (tid < 256 && h > 0) {
            uint32_t cross = (warp < 7) ? wsum[warp + 1] : 0u;
            int S = (int)(v + cross) + cnt_above;   // |{u >= bin tid floor}|
            int Sa = S - (int)h;
            if (S >= TOPK && Sa < TOPK) { sh_bf = tid; sh_cntge = S; sh_above = Sa; }
        }
        __syncthreads();
        if (sh_bf < 0) {
            // fewer than 200 above threshold: take them all (rest never output)
            cnt_ge = cnt_above + (int)wsum[0];
            mode = 0;
            break;
        }
        gLo += ((uint32_t)sh_bf << shift);
        cnt_ge = sh_cntge;
        if (cnt_ge <= CAP) { mode = 0; break; }
        if (shift == 0) {     // exact pivot with massive ties
            pivot = gLo;
            kr = TOPK - sh_above;
            cnt_above = sh_above;
            mode = 1;
            break;
        }
        cnt_above = sh_above;
        shift = (shift >= 8) ? shift - 8 : 0;
        __syncthreads();
    }
    __syncthreads();

    // ---- collect candidates into 64-bit composite keys ----
    if (tid == 0) { ccnt = 0; eq_taken = 0; }
    __syncthreads();
    int used;
    if (mode == 0) {
        for (int i = tid; i < NV; i += NT) {
            float4 v = sc4[i];
            float vv[4] = { v.x, v.y, v.z, v.w };
            #pragma unroll
            for (int k = 0; k < 4; ++k) {
                if (vv[k] > 0.01f) {
                    uint32_t u = f2o(vv[k]);
                    if (u >= gLo) {
                        int p = atomicAdd(&ccnt, 1);
                        ck64[p] = ((unsigned long long)u << 32)
                                | (uint32_t)~(uint32_t)(i * 4 + k);
                    }
                }
            }
        }
        used = cnt_ge;
    } else {
        // strictly greater than pivot
        for (int i = tid; i < NV; i += NT) {
            float4 v = sc4[i];
            float vv[4] = { v.x, v.y, v.z, v.w };
            #pragma unroll
            for (int k = 0; k < 4; ++k) {
                if (vv[k] > 0.01f) {
                    uint32_t u = f2o(vv[k]);
                    if (u > pivot) {
                        int p = atomicAdd(&ccnt, 1);
                        ck64[p] = ((unsigned long long)u << 32)
                                | (uint32_t)~(uint32_t)(i * 4 + k);
                    }
                }
            }
        }
        __syncthreads();
        // append first kr ties by ascending index
        for (int base0 = 0; base0 < N2; base0 += NT) {
            int i = base0 + tid;
            bool eq = false;
            if (i < N2) {
                float s = sc[i];
                eq = (s > 0.01f) && (f2o(s) == pivot);
            }
            unsigned bal = __ballot_sync(0xFFFFFFFFu, eq);
            if (lane == 0) warp_cnt[warp] = __popc(bal);
            __syncthreads();
            int woff = 0;
            #pragma unroll
            for (int w = 0; w < NW; ++w) if (w < warp) woff += warp_cnt[w];
            int rank = eq_taken + woff + __popc(bal & ((1u << lane) - 1u));
            if (eq && rank < kr)
                ck64[cnt_above + rank] = ((unsigned long long)pivot << 32)
                                       | (uint32_t)~(uint32_t)i;
            __syncthreads();
            if (tid == 0) {
                int tot = 0;
                #pragma unroll
                for (int w = 0; w < NW; ++w) tot += warp_cnt[w];
                eq_taken += tot;
            }
            __syncthreads();
            if (eq_taken >= kr) break;
        }
        used = cnt_above + kr;
    }
    __syncthreads();

    // ---- pad + bitonic sort (ascending; rank r lives at slot P-1-r) ----
    int P = 256;
    while (P < used) P <<= 1;
    for (int s = used + tid; s < P; s += NT) ck64[s] = 0ull;
    __syncthreads();
    for (int k = 2; k <= P; k <<= 1) {
        for (int j = k >> 1; j > 0; j >>= 1) {
            for (int i = tid; i < P; i += NT) {
                int ixj = i ^ j;
                if (ixj > i) {
                    bool up = ((i & k) == 0);
                    unsigned long long a = ck64[i], bb2 = ck64[ixj];
                    if ((a > bb2) == up) { ck64[i] = bb2; ck64[ixj] = a; }
                }
            }
            __syncthreads();
        }
    }

    // ---- gather sorted top-200 scores + boxes ----
    if (tid < TOPK) {
        if (tid < used) {
            unsigned long long v = ck64[P - 1 - tid];
            uint32_t key = (uint32_t)(v >> 32);
            uint32_t i = ~((uint32_t)v);
            cscore[tid] = o2f(key);
            const float4 bp = ((const float4*)g_boxes)[(size_t)b * N2 + i];
            cbox[tid * 4 + 0] = bp.x; cbox[tid * 4 + 1] = bp.y;
            cbox[tid * 4 + 2] = bp.z; cbox[tid * 4 + 3] = bp.w;
        } else {
            cscore[tid] = -1.0f;
            cbox[tid * 4 + 0] = 0.f; cbox[tid * 4 + 1] = 0.f;
            cbox[tid * 4 + 2] = 0.f; cbox[tid * 4 + 3] = 0.f;
        }
    }
    // valid bitmap
    {
        bool v = (tid < TOPK) && (tid < used);
        uint32_t bal = __ballot_sync(0xFFFFFFFFu, v);
        if (lane == 0 && warp < KW) validw[warp] = bal;
    }
    __syncthreads();

    // ---- IoU > 0.45 bitmask ----
    for (int t = tid; t < TOPK * KW; t += NT) {
        int j = t / KW, w = t % KW;
        float jx1 = cbox[j * 4 + 0], jy1 = cbox[j * 4 + 1];
        float jx2 = cbox[j * 4 + 2], jy2 = cbox[j * 4 + 3];
        float ja = (jx2 - jx1) * (jy2 - jy1);
        uint32_t m = 0;
        int i0 = w * 32;
        #pragma unroll 4
        for (int q = 0; q < 32; ++q) {
            int i = i0 + q;
            if (i >= TOPK) break;
            float x1 = fmaxf(jx1, cbox[i * 4 + 0]);
            float y1 = fmaxf(jy1, cbox[i * 4 + 1]);
            float x2 = fminf(jx2, cbox[i * 4 + 2]);
            float y2 = fminf(jy2, cbox[i * 4 + 3]);
            float inter = fmaxf(x2 - x1, 0.0f) * fmaxf(y2 - y1, 0.0f);
            float ia = (cbox[i * 4 + 2] - cbox[i * 4 + 0]) * (cbox[i * 4 + 3] - cbox[i * 4 + 1]);
            float iou = inter / (ja + ia - inter);
            if (iou > 0.45f) m |= (1u << q);
        }
        iou_mask[j * KW + w] = m;
    }
    __syncthreads();

    // ---- serial greedy NMS: skip-scan over set bits only ----
    if (tid == 0) {
        uint32_t sup[KW] = {0}, kp[KW] = {0};
        for (int w = 0; w < KW; ++w) {
            uint32_t rem = validw[w] & ~sup[w];
            while (rem) {
                int bit = __ffs(rem) - 1;
                int j = w * 32 + bit;
                kp[w] |= 1u << bit;
                #pragma unroll
                for (int q = 0; q < KW; ++q) sup[q] |= iou_mask[j * KW + q];
                uint32_t done = (bit >= 31) ? 0xFFFFFFFFu : ((2u << bit) - 1u);
                rem = validw[w] & ~sup[w] & ~done;
            }
        }
        #pragma unroll
        for (int q = 0; q < KW; ++q) keepw[q] = kp[q];
    }
    __syncthreads();

    // ---- compacted writes ----
    if (tid < TOPK) {
        int w = tid >> 5, bit = tid & 31;
        if ((keepw[w] >> bit) & 1u) {
            int pos = __popc(keepw[w] & ((1u << bit) - 1u));
            for (int q = 0; q < w; ++q) pos += __popc(keepw[q]);
            float* op = out + (((size_t)b * CC + c) * TOPK + pos) * 5;
            op[0] = cscore[tid];
            op[1] = cbox[tid * 4 + 0]; op[2] = cbox[tid * 4 + 1];
            op[3] = cbox[tid * 4 + 2]; op[4] = cbox[tid * 4 + 3];
        }
    }
}

// ---------------------------------------------------------------------------
extern "C" void kernel_launch(void* const* d_in, const int* in_sizes, int n_in,
                              void* d_out, int out_size) {
    const float* loc1  = (const float*)d_in[0];
    const float* conf1 = (const float*)d_in[1];
    const float* loc2  = (const float*)d_in[2];
    const float* conf2 = (const float*)d_in[3];
    const float* dbox  = (const float*)d_in[4];
    float* out = (float*)d_out;

    cudaMemsetAsync(d_out, 0, (size_t)out_size * sizeof(float), 0);

    int total = BB * NN;
    prep_kernel<<<(total + 255) / 256, 256>>>(loc1, conf1, loc2, conf2, dbox);

    dim3 grid(CC - 1, BB);
    nms_kernel<<<grid, NT>>>(out);
}

// round 7
// speedup vs baseline: 2.2874x; 1.2543x over previous
#include <cuda_runtime.h>
#include <cstdint>

#define BB 32
#define NN 8732
#define CC 21
#define N2 17464          // 2*NN
#define NV (N2/4)         // 4366 uint4s
#define TOPK 200
#define KW 7              // ceil(TOPK/32)
#define NT 512
#define NW (NT/32)
#define CAP 1024
#define STHR 40           // sampled-suffix threshold (-> ~320 est. candidates)

// scratch (allocation-free rule: device globals)
__device__ float    g_boxes[(size_t)BB * N2 * 4];   // [B][2N][4] xyxy
__device__ uint32_t g_keys[(size_t)BB * CC * N2];   // [B][C][2N] orderable keys (0 = below thresh)

__device__ __forceinline__ float o2f(uint32_t u) {
    // inverse of (bits | 0x80000000) for positive floats
    return __uint_as_float(u & 0x7FFFFFFFu);
}

// ---------------------------------------------------------------------------
// Kernel 1: decode boxes (both views, view2 flipped) + softmax both views
// ---------------------------------------------------------------------------
__global__ __launch_bounds__(256) void prep_kernel(
    const float* __restrict__ loc1, const float* __restrict__ conf1,
    const float* __restrict__ loc2, const float* __restrict__ conf2,
    const float* __restrict__ dbox)
{
    int idx = blockIdx.x * 256 + threadIdx.x;
    if (idx >= BB * NN) return;
    int b = idx / NN, n = idx % NN;

    float4 d4 = ((const float4*)dbox)[n];
    float dcx = d4.x, dcy = d4.y, dw = d4.z, dh = d4.w;

    {
        float4 l = ((const float4*)loc1)[idx];
        float cx = dcx + (l.x * 0.1f) * dw;
        float cy = dcy + (l.y * 0.1f) * dh;
        float w = dw * expf(l.z * 0.2f);
        float h = dh * expf(l.w * 0.2f);
        float4 o;
        o.x = cx - w * 0.5f; o.y = cy - h * 0.5f;
        o.z = cx + w * 0.5f; o.w = cy + h * 0.5f;
        ((float4*)g_boxes)[(size_t)b * N2 + n] = o;
    }
    {
        float4 l = ((const float4*)loc2)[idx];
        float cx = dcx + (l.x * 0.1f) * dw;
        float cy = dcy + (l.y * 0.1f) * dh;
        float w = dw * expf(l.z * 0.2f);
        float h = dh * expf(l.w * 0.2f);
        float x1 = cx - w * 0.5f, x2 = cx + w * 0.5f;
        float4 o;
        o.x = 1.0f - x2; o.y = cy - h * 0.5f;
        o.z = 1.0f - x1; o.w = cy + h * 0.5f;
        ((float4*)g_boxes)[(size_t)b * N2 + NN + n] = o;
    }
    {
        const float* cf = conf1 + (size_t)idx * CC;
        float mx = cf[0];
        #pragma unroll
        for (int j = 1; j < CC; ++j) mx = fmaxf(mx, cf[j]);
        float e[CC]; float sum = 0.0f;
        #pragma unroll
        for (int j = 0; j < CC; ++j) { e[j] = expf(cf[j] - mx); sum += e[j]; }
        uint32_t* sb = g_keys + (size_t)b * CC * N2 + n;
        #pragma unroll
        for (int j = 0; j < CC; ++j) {
            float p = e[j] / sum;
            sb[(size_t)j * N2] = (p > 0.01f) ? (__float_as_uint(p) | 0x80000000u) : 0u;
        }
    }
    {
        const float* cf = conf2 + (size_t)idx * CC;
        float mx = cf[0];
        #pragma unroll
        for (int j = 1; j < CC; ++j) mx = fmaxf(mx, cf[j]);
        float e[CC]; float sum = 0.0f;
        #pragma unroll
        for (int j = 0; j < CC; ++j) { e[j] = expf(cf[j] - mx); sum += e[j]; }
        uint32_t* sb = g_keys + (size_t)b * CC * N2 + NN + n;
        #pragma unroll
        for (int j = 0; j < CC; ++j) {
            float p = e[j] / sum;
            sb[(size_t)j * N2] = (p > 0.01f) ? (__float_as_uint(p) | 0x80000000u) : 0u;
        }
    }
}

// ---------------------------------------------------------------------------
// Kernel 2: per (b, class>=1): top-200 (stable), NMS, compacted output
// ---------------------------------------------------------------------------
__global__ __launch_bounds__(NT, 4) void nms_kernel(float* __restrict__ out)
{
    const int c = blockIdx.x + 1;   // classes 1..20
    const int b = blockIdx.y;
    const int tid = threadIdx.x;
    const int lane = tid & 31, warp = tid >> 5;

    __shared__ uint32_t hist[256];
    __shared__ uint32_t wsum[8];
    __shared__ unsigned long long ck64[CAP];
    __shared__ float bx1[TOPK], by1[TOPK], bx2[TOPK], by2[TOPK];
    __shared__ float cscore[TOPK];
    __shared__ uint32_t iou_mask[TOPK * KW];
    __shared__ int sh_bin;
    __shared__ int ccnt, eq_taken;
    __shared__ int sh_bf, sh_S, sh_Sa;
    __shared__ int warp_cnt[NW];
    __shared__ uint32_t validw[KW], keepw[KW];

    const uint32_t* su = g_keys + ((size_t)b * CC + c) * N2;
    const uint4* su4 = (const uint4*)su;
    const uint32_t gLo = (__float_as_uint(0.01f) | 0x80000000u) + 1u;  // min valid key

    // ================= sampled histogram (1/8 stride) =================
    if (tid < 256) hist[tid] = 0;
    if (tid == 0) { sh_bin = -1; ccnt = 0; eq_taken = 0; }
    __syncthreads();
    for (int i = tid; i < N2 / 8; i += NT) {
        uint32_t u = su[i << 3];
        if (u >= gLo) {
            uint32_t r = (u - gLo) >> 18;
            if (r > 255u) r = 255u;
            atomicAdd(&hist[r], 1u);
        }
    }
    __syncthreads();
    // inclusive suffix scan of 256 bins
    {
        uint32_t h = (tid < 256) ? hist[tid] : 0u;
        uint32_t v = h;
        #pragma unroll
        for (int off = 1; off < 32; off <<= 1) {
            uint32_t o = __shfl_down_sync(0xFFFFFFFFu, v, off);
            if (lane + off < 32) v += o;
        }
        if (tid < 256 && lane == 0) wsum[warp] = v;
        __syncthreads();
        if (warp == 0 && lane < 8) {
            uint32_t w8 = wsum[lane];
            #pragma unroll
            for (int off = 1; off < 8; off <<= 1) {
                uint32_t o = __shfl_down_sync(0xFFu, w8, off, 8);
                if (lane + off < 8) w8 += o;
            }
            wsum[lane] = w8;
        }
        __syncthreads();
        if (tid < 256) {
            uint32_t cross = (warp < 7) ? wsum[warp + 1] : 0u;
            uint32_t S = v + cross;           // suffix(tid)
            uint32_t Snext = S - h;           // suffix(tid+1)
            if (S >= STHR && Snext < STHR) sh_bin = tid;  // largest bin w/ suffix>=STHR
        }
        __syncthreads();
    }
    uint32_t pivot = (sh_bin >= 0) ? (gLo + ((uint32_t)sh_bin << 18)) : gLo;

    // ================= single full collect sweep =================
    for (int i0 = tid * 2; i0 < NV; i0 += NT * 2) {
        uint4 a = su4[i0];
        uint4 a2 = su4[i0 + 1];
        uint32_t ua[8] = { a.x, a.y, a.z, a.w, a2.x, a2.y, a2.z, a2.w };
        #pragma unroll
        for (int k = 0; k < 8; ++k) {
            if (ua[k] >= pivot) {
                int p = atomicAdd(&ccnt, 1);
                if (p < CAP)
                    ck64[p] = ((unsigned long long)ua[k] << 32)
                            | (uint32_t)~(uint32_t)(i0 * 4 + k);
            }
        }
    }
    __syncthreads();
    int nact = ccnt;
    bool ok = (nact <= CAP) && (nact >= TOPK || pivot == gLo);
    int used;

    if (ok) {
        used = nact;
    } else {
        // ============ exact fallback (rare): multi-level radix ============
        uint32_t fLo = gLo;
        int shift = 18, nbins = 256, cnt_above = 0, cnt_ge = 0, mode = 0, kr = 0;
        uint32_t fpivot = 0;
        for (;;) {
            if (tid < 256) hist[tid] = 0;
            if (tid == 0) sh_bf = -1;
            __syncthreads();
            for (int i = tid; i < N2; i += NT) {
                uint32_t u = su[i];
                if (u >= fLo) {
                    uint32_t r = (u - fLo) >> shift;
                    if (r < (uint32_t)nbins) atomicAdd(&hist[r], 1u);
                }
            }
            __syncthreads();
            uint32_t h = (tid < 256) ? hist[tid] : 0u;
            uint32_t v = h;
            #pragma unroll
            for (int off = 1; off < 32; off <<= 1) {
                uint32_t o = __shfl_down_sync(0xFFFFFFFFu, v, off);
                if (lane + off < 32) v += o;
            }
            if (tid < 256 && lane == 0) wsum[warp] = v;
            __syncthreads();
            if (warp == 0 && lane < 8) {
                uint32_t w8 = wsum[lane];
                #pragma unroll
                for (int off = 1; off < 8; off <<= 1) {
                    uint32_t o = __shfl_down_sync(0xFFu, w8, off, 8);
                    if (lane + off < 8) w8 += o;
                }
                wsum[lane] = w8;
            }
            __syncthreads();
            if (tid < 256 && h > 0) {
                uint32_t cross = (warp < 7) ? wsum[warp + 1] : 0u;
                int S = (int)(v + cross) + cnt_above;
                int Sa = S - (int)h;
                if (S >= TOPK && Sa < TOPK) { sh_bf = tid; sh_S = S; sh_Sa = Sa; }
            }
            __syncthreads();
            if (sh_bf < 0) {            // fewer than TOPK valid overall
                cnt_ge = cnt_above + (int)wsum[0];
                mode = 0;
                break;
            }
            fLo += ((uint32_t)sh_bf << shift);
            cnt_ge = sh_S;
            if (cnt_ge <= CAP) { mode = 0; break; }
            if (shift == 0) {           // massive exact ties
                fpivot = fLo; kr = TOPK - sh_Sa; cnt_above = sh_Sa; mode = 1;
                break;
            }
            cnt_above = sh_Sa;
            int ns = (shift >= 8) ? shift - 8 : 0;
            nbins = 1 << (shift - ns);
            shift = ns;
            __syncthreads();
        }
        __syncthreads();
        if (tid == 0) { ccnt = 0; eq_taken = 0; }
        __syncthreads();
        if (mode == 0) {
            for (int i = tid; i < N2; i += NT) {
                uint32_t u = su[i];
                if (u >= fLo) {
                    int p = atomicAdd(&ccnt, 1);
                    if (p < CAP)
                        ck64[p] = ((unsigned long long)u << 32) | (uint32_t)~(uint32_t)i;
                }
            }
            used = cnt_ge;
        } else {
            for (int i = tid; i < N2; i += NT) {
                uint32_t u = su[i];
                if (u > fpivot) {
                    int p = atomicAdd(&ccnt, 1);
                    if (p < CAP)
                        ck64[p] = ((unsigned long long)u << 32) | (uint32_t)~(uint32_t)i;
                }
            }
            __syncthreads();
            // append first kr ties by ascending index
            for (int base0 = 0; base0 < N2; base0 += NT) {
                int i = base0 + tid;
                bool eq = (i < N2) && (su[i] == fpivot);
                unsigned bal = __ballot_sync(0xFFFFFFFFu, eq);
                if (lane == 0) warp_cnt[warp] = __popc(bal);
                __syncthreads();
                int woff = 0;
                #pragma unroll
                for (int w = 0; w < NW; ++w) if (w < warp) woff += warp_cnt[w];
                int rank = eq_taken + woff + __popc(bal & ((1u << lane) - 1u));
                if (eq && rank < kr)
                    ck64[cnt_above + rank] = ((unsigned long long)fpivot << 32)
                                           | (uint32_t)~(uint32_t)i;
                __syncthreads();
                if (tid == 0) {
                    int tot = 0;
                    #pragma unroll
                    for (int w = 0; w < NW; ++w) tot += warp_cnt[w];
                    eq_taken += tot;
                }
                __syncthreads();
                if (eq_taken >= kr) break;
            }
            used = cnt_above + kr;
        }
    }
    __syncthreads();

    // ---- pad + bitonic sort (ascending; rank r lives at slot P-1-r) ----
    int P = 256;
    while (P < used) P <<= 1;
    for (int s = used + tid; s < P; s += NT) ck64[s] = 0ull;
    __syncthreads();
    for (int k = 2; k <= P; k <<= 1) {
        for (int j = k >> 1; j > 0; j >>= 1) {
            for (int i = tid; i < P; i += NT) {
                int ixj = i ^ j;
                if (ixj > i) {
                    bool up = ((i & k) == 0);
                    unsigned long long a = ck64[i], bb2 = ck64[ixj];
                    if ((a > bb2) == up) { ck64[i] = bb2; ck64[ixj] = a; }
                }
            }
            __syncthreads();
        }
    }

    // ---- gather sorted top-200 scores + boxes (SoA) ----
    if (tid < TOPK) {
        if (tid < used) {
            unsigned long long v = ck64[P - 1 - tid];
            uint32_t key = (uint32_t)(v >> 32);
            uint32_t i = ~((uint32_t)v);
            cscore[tid] = o2f(key);
            const float4 bp = ((const float4*)g_boxes)[(size_t)b * N2 + i];
            bx1[tid] = bp.x; by1[tid] = bp.y; bx2[tid] = bp.z; by2[tid] = bp.w;
        } else {
            cscore[tid] = -1.0f;
            bx1[tid] = 0.f; by1[tid] = 0.f; bx2[tid] = 0.f; by2[tid] = 0.f;
        }
    }
    {
        bool v = (tid < TOPK) && (tid < used);
        uint32_t bal = __ballot_sync(0xFFFFFFFFu, v);
        if (lane == 0 && warp < KW) validw[warp] = bal;
    }
    __syncthreads();

    // ---- IoU > 0.45 bitmask, upper triangle only (i > j) ----
    for (int t = tid; t < TOPK * KW; t += NT) {
        int j = t / KW, w = t - j * KW;
        int i0 = w * 32;
        uint32_t m = 0;
        if (i0 + 31 > j) {
            float jx1 = bx1[j], jy1 = by1[j], jx2 = bx2[j], jy2 = by2[j];
            float ja = (jx2 - jx1) * (jy2 - jy1);
            int qs = (j >= i0) ? (j - i0 + 1) : 0;
            for (int q = qs; q < 32; ++q) {
                int i = i0 + q;
                if (i >= TOPK) break;
                float x1 = fmaxf(jx1, bx1[i]);
                float y1 = fmaxf(jy1, by1[i]);
                float x2 = fminf(jx2, bx2[i]);
                float y2 = fminf(jy2, by2[i]);
                float inter = fmaxf(x2 - x1, 0.0f) * fmaxf(y2 - y1, 0.0f);
                float ia = (bx2[i] - bx1[i]) * (by2[i] - by1[i]);
                float iou = inter / (ja + ia - inter);
                if (iou > 0.45f) m |= (1u << q);
            }
        }
        iou_mask[j * KW + w] = m;
    }
    __syncthreads();

    // ---- serial greedy NMS: skip-scan over set bits only ----
    if (tid == 0) {
        uint32_t sup[KW] = {0}, kp[KW] = {0};
        for (int w = 0; w < KW; ++w) {
            uint32_t rem = validw[w] & ~sup[w];
            while (rem) {
                int bit = __ffs(rem) - 1;
                int j = w * 32 + bit;
                kp[w] |= 1u << bit;
                #pragma unroll
                for (int q = 0; q < KW; ++q) sup[q] |= iou_mask[j * KW + q];
                uint32_t done = (bit >= 31) ? 0xFFFFFFFFu : ((2u << bit) - 1u);
                rem = validw[w] & ~sup[w] & ~done;
            }
        }
        #pragma unroll
        for (int q = 0; q < KW; ++q) keepw[q] = kp[q];
    }
    __syncthreads();

    // ---- compacted writes ----
    if (tid < TOPK) {
        int w = tid >> 5, bit = tid & 31;
        if ((keepw[w] >> bit) & 1u) {
            int pos = __popc(keepw[w] & ((1u << bit) - 1u));
            for (int q = 0; q < w; ++q) pos += __popc(keepw[q]);
            float* op = out + (((size_t)b * CC + c) * TOPK + pos) * 5;
            op[0] = cscore[tid];
            op[1] = bx1[tid]; op[2] = by1[tid];
            op[3] = bx2[tid]; op[4] = by2[tid];
        }
    }
}

// ---------------------------------------------------------------------------
extern "C" void kernel_launch(void* const* d_in, const int* in_sizes, int n_in,
                              void* d_out, int out_size) {
    const float* loc1  = (const float*)d_in[0];
    const float* conf1 = (const float*)d_in[1];
    const float* loc2  = (const float*)d_in[2];
    const float* conf2 = (const float*)d_in[3];
    const float* dbox  = (const float*)d_in[4];
    float* out = (float*)d_out;

    cudaMemsetAsync(d_out, 0, (size_t)out_size * sizeof(float), 0);

    int total = BB * NN;
    prep_kernel<<<(total + 255) / 256, 256>>>(loc1, conf1, loc2, conf2, dbox);

    dim3 grid(CC - 1, BB);
    nms_kernel<<<grid, NT>>>(out);
}

// round 11
// speedup vs baseline: 2.9580x; 1.2932x over previous
#include <cuda_runtime.h>
#include <cstdint>

#define BB 32
#define NN 8732
#define CC 21
#define N2 17464          // 2*NN
#define NV (N2/4)         // 4366 uint4s
#define TOPK 200
#define KW 7              // ceil(TOPK/32)
#define NT 512
#define NW (NT/32)
#define CAP 1024
#define STHR 40           // sampled-suffix threshold (-> ~320 est. candidates)

// scratch (allocation-free rule: device globals)
__device__ float    g_boxes[(size_t)BB * N2 * 4];   // [B][2N][4] xyxy
__device__ uint32_t g_keys[(size_t)BB * CC * N2];   // [B][C][2N] orderable keys (0 = below thresh)

__device__ __forceinline__ float o2f(uint32_t u) {
    return __uint_as_float(u & 0x7FFFFFFFu);
}
__device__ __forceinline__ unsigned long long my_u64min(unsigned long long a, unsigned long long b) {
    return a < b ? a : b;
}
__device__ __forceinline__ unsigned long long my_u64max(unsigned long long a, unsigned long long b) {
    return a > b ? a : b;
}

// ---------------------------------------------------------------------------
// Kernel 1: decode boxes (both views, view2 flipped) + softmax both views
// ---------------------------------------------------------------------------
__global__ __launch_bounds__(256) void prep_kernel(
    const float* __restrict__ loc1, const float* __restrict__ conf1,
    const float* __restrict__ loc2, const float* __restrict__ conf2,
    const float* __restrict__ dbox)
{
    int idx = blockIdx.x * 256 + threadIdx.x;
    if (idx >= BB * NN) return;
    int b = idx / NN, n = idx % NN;

    float4 d4 = ((const float4*)dbox)[n];
    float dcx = d4.x, dcy = d4.y, dw = d4.z, dh = d4.w;

    {
        float4 l = ((const float4*)loc1)[idx];
        float cx = dcx + (l.x * 0.1f) * dw;
        float cy = dcy + (l.y * 0.1f) * dh;
        float w = dw * expf(l.z * 0.2f);
        float h = dh * expf(l.w * 0.2f);
        float4 o;
        o.x = cx - w * 0.5f; o.y = cy - h * 0.5f;
        o.z = cx + w * 0.5f; o.w = cy + h * 0.5f;
        ((float4*)g_boxes)[(size_t)b * N2 + n] = o;
    }
    {
        float4 l = ((const float4*)loc2)[idx];
        float cx = dcx + (l.x * 0.1f) * dw;
        float cy = dcy + (l.y * 0.1f) * dh;
        float w = dw * expf(l.z * 0.2f);
        float h = dh * expf(l.w * 0.2f);
        float x1 = cx - w * 0.5f, x2 = cx + w * 0.5f;
        float4 o;
        o.x = 1.0f - x2; o.y = cy - h * 0.5f;
        o.z = 1.0f - x1; o.w = cy + h * 0.5f;
        ((float4*)g_boxes)[(size_t)b * N2 + NN + n] = o;
    }
    {
        const float* cf = conf1 + (size_t)idx * CC;
        float mx = cf[0];
        #pragma unroll
        for (int j = 1; j < CC; ++j) mx = fmaxf(mx, cf[j]);
        float e[CC]; float sum = 0.0f;
        #pragma unroll
        for (int j = 0; j < CC; ++j) { e[j] = expf(cf[j] - mx); sum += e[j]; }
        uint32_t* sb = g_keys + (size_t)b * CC * N2 + n;
        #pragma unroll
        for (int j = 0; j < CC; ++j) {
            float p = e[j] / sum;
            sb[(size_t)j * N2] = (p > 0.01f) ? (__float_as_uint(p) | 0x80000000u) : 0u;
        }
    }
    {
        const float* cf = conf2 + (size_t)idx * CC;
        float mx = cf[0];
        #pragma unroll
        for (int j = 1; j < CC; ++j) mx = fmaxf(mx, cf[j]);
        float e[CC]; float sum = 0.0f;
        #pragma unroll
        for (int j = 0; j < CC; ++j) { e[j] = expf(cf[j] - mx); sum += e[j]; }
        uint32_t* sb = g_keys + (size_t)b * CC * N2 + NN + n;
        #pragma unroll
        for (int j = 0; j < CC; ++j) {
            float p = e[j] / sum;
            sb[(size_t)j * N2] = (p > 0.01f) ? (__float_as_uint(p) | 0x80000000u) : 0u;
        }
    }
}

// ---------------------------------------------------------------------------
// Kernel 2: per (b, class>=1): top-200 (stable), NMS, compacted output
// ---------------------------------------------------------------------------
__global__ __launch_bounds__(NT, 4) void nms_kernel(float* __restrict__ out)
{
    const int c = blockIdx.x + 1;   // classes 1..20
    const int b = blockIdx.y;
    const int tid = threadIdx.x;
    const int lane = tid & 31, warp = tid >> 5;

    __shared__ uint32_t hist[256];
    __shared__ uint32_t wsum[8];
    __shared__ unsigned long long ck64[CAP];
    __shared__ float4 cb4[TOPK];
    __shared__ float cscore[TOPK];
    __shared__ uint32_t iou_mask[TOPK * KW];
    __shared__ int sh_bin;
    __shared__ int ccnt, eq_taken;
    __shared__ int sh_bf, sh_S, sh_Sa;
    __shared__ int warp_cnt[NW];
    __shared__ uint32_t validw[KW], keepw[KW];

    const uint32_t* su = g_keys + ((size_t)b * CC + c) * N2;
    const uint4* su4 = (const uint4*)su;
    const uint32_t gLo = (__float_as_uint(0.01f) | 0x80000000u) + 1u;  // min valid key

    // ================= sampled histogram (1/8 stride) =================
    if (tid < 256) hist[tid] = 0;
    if (tid == 0) { sh_bin = -1; ccnt = 0; eq_taken = 0; }
    __syncthreads();
    for (int i = tid; i < N2 / 8; i += NT) {
        uint32_t u = su[i << 3];
        if (u >= gLo) {
            uint32_t r = (u - gLo) >> 18;
            if (r > 255u) r = 255u;
            atomicAdd(&hist[r], 1u);
        }
    }
    __syncthreads();
    {   // inclusive suffix scan of 256 bins
        uint32_t h = (tid < 256) ? hist[tid] : 0u;
        uint32_t v = h;
        #pragma unroll
        for (int off = 1; off < 32; off <<= 1) {
            uint32_t o = __shfl_down_sync(0xFFFFFFFFu, v, off);
            if (lane + off < 32) v += o;
        }
        if (tid < 256 && lane == 0) wsum[warp] = v;
        __syncthreads();
        if (warp == 0 && lane < 8) {
            uint32_t w8 = wsum[lane];
            #pragma unroll
            for (int off = 1; off < 8; off <<= 1) {
                uint32_t o = __shfl_down_sync(0xFFu, w8, off, 8);
                if (lane + off < 8) w8 += o;
            }
            wsum[lane] = w8;
        }
        __syncthreads();
        if (tid < 256) {
            uint32_t cross = (warp < 7) ? wsum[warp + 1] : 0u;
            uint32_t S = v + cross;
            uint32_t Snext = S - h;
            if (S >= STHR && Snext < STHR) sh_bin = tid;
        }
        __syncthreads();
    }
    uint32_t pivot = (sh_bin >= 0) ? (gLo + ((uint32_t)sh_bin << 18)) : gLo;

    // ================= single full collect sweep =================
    for (int i0 = tid * 2; i0 < NV; i0 += NT * 2) {
        uint4 a = su4[i0];
        uint4 a2 = su4[i0 + 1];
        uint32_t ua[8] = { a.x, a.y, a.z, a.w, a2.x, a2.y, a2.z, a2.w };
        #pragma unroll
        for (int k = 0; k < 8; ++k) {
            if (ua[k] >= pivot) {
                int p = atomicAdd(&ccnt, 1);
                if (p < CAP)
                    ck64[p] = ((unsigned long long)ua[k] << 32)
                            | (uint32_t)~(uint32_t)(i0 * 4 + k);
            }
        }
    }
    __syncthreads();
    int nact = ccnt;
    bool ok = (nact <= CAP) && (nact >= TOPK || pivot == gLo);
    int used;

    if (ok) {
        used = nact;
    } else {
        // ============ exact fallback (rare): multi-level radix ============
        uint32_t fLo = gLo;
        int shift = 18, nbins = 256, cnt_above = 0, cnt_ge = 0, mode = 0, kr = 0;
        uint32_t fpivot = 0;
        for (;;) {
            if (tid < 256) hist[tid] = 0;
            if (tid == 0) sh_bf = -1;
            __syncthreads();
            for (int i = tid; i < N2; i += NT) {
                uint32_t u = su[i];
                if (u >= fLo) {
                    uint32_t r = (u - fLo) >> shift;
                    if (r < (uint32_t)nbins) atomicAdd(&hist[r], 1u);
                }
            }
            __syncthreads();
            uint32_t h = (tid < 256) ? hist[tid] : 0u;
            uint32_t v = h;
            #pragma unroll
            for (int off = 1; off < 32; off <<= 1) {
                uint32_t o = __shfl_down_sync(0xFFFFFFFFu, v, off);
                if (lane + off < 32) v += o;
            }
            if (tid < 256 && lane == 0) wsum[warp] = v;
            __syncthreads();
            if (warp == 0 && lane < 8) {
                uint32_t w8 = wsum[lane];
                #pragma unroll
                for (int off = 1; off < 8; off <<= 1) {
                    uint32_t o = __shfl_down_sync(0xFFu, w8, off, 8);
                    if (lane + off < 8) w8 += o;
                }
                wsum[lane] = w8;
            }
            __syncthreads();
            if (tid < 256 && h > 0) {
                uint32_t cross = (warp < 7) ? wsum[warp + 1] : 0u;
                int S = (int)(v + cross) + cnt_above;
                int Sa = S - (int)h;
                if (S >= TOPK && Sa < TOPK) { sh_bf = tid; sh_S = S; sh_Sa = Sa; }
            }
            __syncthreads();
            if (sh_bf < 0) {
                cnt_ge = cnt_above + (int)wsum[0];
                mode = 0;
                break;
            }
            fLo += ((uint32_t)sh_bf << shift);
            cnt_ge = sh_S;
            if (cnt_ge <= CAP) { mode = 0; break; }
            if (shift == 0) {
                fpivot = fLo; kr = TOPK - sh_Sa; cnt_above = sh_Sa; mode = 1;
                break;
            }
            cnt_above = sh_Sa;
            int ns = (shift >= 8) ? shift - 8 : 0;
            nbins = 1 << (shift - ns);
            shift = ns;
            __syncthreads();
        }
        __syncthreads();
        if (tid == 0) { ccnt = 0; eq_taken = 0; }
        __syncthreads();
        if (mode == 0) {
            for (int i = tid; i < N2; i += NT) {
                uint32_t u = su[i];
                if (u >= fLo) {
                    int p = atomicAdd(&ccnt, 1);
                    if (p < CAP)
                        ck64[p] = ((unsigned long long)u << 32) | (uint32_t)~(uint32_t)i;
                }
            }
            used = cnt_ge;
        } else {
            for (int i = tid; i < N2; i += NT) {
                uint32_t u = su[i];
                if (u > fpivot) {
                    int p = atomicAdd(&ccnt, 1);
                    if (p < CAP)
                        ck64[p] = ((unsigned long long)u << 32) | (uint32_t)~(uint32_t)i;
                }
            }
            __syncthreads();
            for (int base0 = 0; base0 < N2; base0 += NT) {
                int i = base0 + tid;
                bool eq = (i < N2) && (su[i] == fpivot);
                unsigned bal = __ballot_sync(0xFFFFFFFFu, eq);
                if (lane == 0) warp_cnt[warp] = __popc(bal);
                __syncthreads();
                int woff = 0;
                #pragma unroll
                for (int w = 0; w < NW; ++w) if (w < warp) woff += warp_cnt[w];
                int rank = eq_taken + woff + __popc(bal & ((1u << lane) - 1u));
                if (eq && rank < kr)
                    ck64[cnt_above + rank] = ((unsigned long long)fpivot << 32)
                                           | (uint32_t)~(uint32_t)i;
                __syncthreads();
                if (tid == 0) {
                    int tot = 0;
                    #pragma unroll
                    for (int w = 0; w < NW; ++w) tot += warp_cnt[w];
                    eq_taken += tot;
                }
                __syncthreads();
                if (eq_taken >= kr) break;
            }
            used = cnt_above + kr;
        }
    }
    __syncthreads();

    // ---- sort descending by (key, ~idx); rank r at slot P-1-r ----
    int P;
    if (used <= 512) {
        // fast path: P=512, 1 element/thread, shfl for j<=16
        P = 512;
        for (int s = used + tid; s < 512; s += NT) ck64[s] = 0ull;
        __syncthreads();
        unsigned long long e = ck64[tid];
        // rounds k=2..32: fully in-register
        #pragma unroll
        for (int k = 2; k <= 32; k <<= 1) {
            #pragma unroll
            for (int j = k >> 1; j > 0; j >>= 1) {
                unsigned long long p = __shfl_xor_sync(0xFFFFFFFFu, e, j);
                bool takeMin = (((tid & j) == 0) == ((tid & k) == 0));
                e = takeMin ? my_u64min(e, p) : my_u64max(e, p);
            }
        }
        // rounds k=64..512
        #pragma unroll
        for (int k = 64; k <= 512; k <<= 1) {
            for (int j = k >> 1; j >= 32; j >>= 1) {
                ck64[tid] = e; __syncthreads();
                unsigned long long p = ck64[tid ^ j]; __syncthreads();
                bool takeMin = (((tid & j) == 0) == ((tid & k) == 0));
                e = takeMin ? my_u64min(e, p) : my_u64max(e, p);
            }
            #pragma unroll
            for (int j = 16; j > 0; j >>= 1) {
                unsigned long long p = __shfl_xor_sync(0xFFFFFFFFu, e, j);
                bool takeMin = (((tid & j) == 0) == ((tid & k) == 0));
                e = takeMin ? my_u64min(e, p) : my_u64max(e, p);
            }
        }
        ck64[tid] = e;
        __syncthreads();
    } else {
        P = 1024;
        for (int s = used + tid; s < P; s += NT) ck64[s] = 0ull;
        __syncthreads();
        for (int k = 2; k <= P; k <<= 1) {
            for (int j = k >> 1; j > 0; j >>= 1) {
                for (int i = tid; i < P; i += NT) {
                    int ixj = i ^ j;
                    if (ixj > i) {
                        bool up = ((i & k) == 0);
                        unsigned long long a = ck64[i], bb2 = ck64[ixj];
                        if ((a > bb2) == up) { ck64[i] = bb2; ck64[ixj] = a; }
                    }
                }
                __syncthreads();
            }
        }
    }

    // ---- gather sorted top-200 scores + boxes (float4 AoS) ----
    if (tid < TOPK) {
        if (tid < used) {
            unsigned long long v = ck64[P - 1 - tid];
            uint32_t key = (uint32_t)(v >> 32);
            uint32_t i = ~((uint32_t)v);
            cscore[tid] = o2f(key);
            cb4[tid] = ((const float4*)g_boxes)[(size_t)b * N2 + i];
        } else {
            cscore[tid] = -1.0f;
            cb4[tid] = make_float4(0.f, 0.f, 0.f, 0.f);
        }
    }
    {
        bool v = (tid < TOPK) && (tid < used);
        uint32_t bal = __ballot_sync(0xFFFFFFFFu, v);
        if (lane == 0 && warp < KW) validw[warp] = bal;
    }
    __syncthreads();

    // ---- IoU > 0.45 bitmask, upper triangle only (i > j) ----
    // guarded FMA test, exactly equivalent to fl(inter/union) > 0.45f
    for (int t = tid; t < TOPK * KW; t += NT) {
        int j = t / KW, w = t - j * KW;
        int i0 = w * 32;
        uint32_t m = 0;
        if (i0 + 31 > j) {
            float4 J = cb4[j];
            float ja = (J.z - J.x) * (J.w - J.y);
            int qs = (j >= i0) ? (j - i0 + 1) : 0;
            for (int q = qs; q < 32; ++q) {
                int i = i0 + q;
                if (i >= TOPK) break;
                float4 I = cb4[i];
                float x1 = fmaxf(J.x, I.x);
                float y1 = fmaxf(J.y, I.y);
                float x2 = fminf(J.z, I.z);
                float y2 = fminf(J.w, I.w);
                float inter = fmaxf(x2 - x1, 0.0f) * fmaxf(y2 - y1, 0.0f);
                float ia = (I.z - I.x) * (I.w - I.y);
                float un = ja + ia - inter;
                float tt = fmaf(-0.45f, un, inter);     // inter - 0.45*union, 1 rounding
                float g = 5.96046448e-8f * un;          // 2^-24 * union guard band
                bool dec;
                if (tt > g) dec = true;
                else if (tt < -g) dec = false;
                else dec = (inter / un) > 0.45f;        // exact boundary fallback
                if (dec) m |= (1u << q);
            }
        }
        iou_mask[t] = m;
    }
    __syncthreads();

    // ---- warp-cooperative greedy NMS (warp 0, lanes hold words) ----
    if (warp == 0) {
        uint32_t valid = (lane < KW) ? validw[lane] : 0u;
        uint32_t sup = 0u, kp = 0u;
        for (;;) {
            uint32_t rem = valid & ~sup;
            uint32_t has = __ballot_sync(0xFFFFFFFFu, rem != 0u);
            if (!has) break;
            int w0 = __ffs(has) - 1;
            uint32_t remw = __shfl_sync(0xFFFFFFFFu, rem, w0);
            int bit = __ffs(remw) - 1;
            int j = w0 * 32 + bit;
            if (lane == w0) { kp |= 1u << bit; sup |= 1u << bit; }
            uint32_t mr = (lane < KW) ? iou_mask[j * KW + lane] : 0u;
            sup |= mr;
        }
        if (lane < KW) keepw[lane] = kp;
    }
    __syncthreads();

    // ---- compacted writes ----
    if (tid < TOPK) {
        int w = tid >> 5, bit = tid & 31;
        if ((keepw[w] >> bit) & 1u) {
            int pos = __popc(keepw[w] & ((1u << bit) - 1u));
            for (int q = 0; q < w; ++q) pos += __popc(keepw[q]);
            float4 bp = cb4[tid];
            float* op = out + (((size_t)b * CC + c) * TOPK + pos) * 5;
            op[0] = cscore[tid];
            op[1] = bp.x; op[2] = bp.y;
            op[3] = bp.z; op[4] = bp.w;
        }
    }
}

// ---------------------------------------------------------------------------
extern "C" void kernel_launch(void* const* d_in, const int* in_sizes, int n_in,
                              void* d_out, int out_size) {
    const float* loc1  = (const float*)d_in[0];
    const float* conf1 = (const float*)d_in[1];
    const float* loc2  = (const float*)d_in[2];
    const float* conf2 = (const float*)d_in[3];
    const float* dbox  = (const float*)d_in[4];
    float* out = (float*)d_out;

    cudaMemsetAsync(d_out, 0, (size_t)out_size * sizeof(float), 0);

    int total = BB * NN;
    prep_kernel<<<(total + 255) / 256, 256>>>(loc1, conf1, loc2, conf2, dbox);

    dim3 grid(CC - 1, BB);
    nms_kernel<<<grid, NT>>>(out);
}